// round 1
// baseline (speedup 1.0000x reference)
#include <cuda_runtime.h>
#include <math.h>

#define RR 32
#define CC 32
#define BB 128
#define DD 128
#define HH 128
#define GG 1024

// Scratch: precomputed input-gate contributions (permuted gate layout), 512 MB
__device__ float g_xg[(size_t)RR * CC * BB * GG];
// State carries, double-buffered by diagonal parity: [parity][row/col][batch][H]
__device__ float g_hrow[2 * 32 * BB * HH];
__device__ float g_crow[2 * 32 * BB * HH];
__device__ float g_hcol[2 * 32 * BB * HH];
__device__ float g_ccol[2 * 32 * BB * HH];

__device__ __forceinline__ float sigm(float x) { return 1.0f / (1.0f + expf(-x)); }

// ---------------------------------------------------------------------------
// Zero all state buffers (fresh launch must start from h0 = c0 = 0)
// ---------------------------------------------------------------------------
__global__ void k_zero() {
    int t = blockIdx.x * blockDim.x + threadIdx.x;  // 262144 float4 per array
    float4 z = make_float4(0.f, 0.f, 0.f, 0.f);
    if (t < 2 * 32 * BB * HH / 4) {
        reinterpret_cast<float4*>(g_hrow)[t] = z;
        reinterpret_cast<float4*>(g_crow)[t] = z;
        reinterpret_cast<float4*>(g_hcol)[t] = z;
        reinterpret_cast<float4*>(g_ccol)[t] = z;
    }
}

// ---------------------------------------------------------------------------
// Phase 1: xg[cell][m][p] = sum_k x[cell][m][k] * w_ih[grow(p)][k] + b_ih + b_hh
// where permuted column p in [0,1024): unit u = p>>2, gate g = p&3,
// global gate row grow(p) = g*256 + u.
// grid = (8 n-tiles, 1024 cells), 256 threads, 8x8 register tile.
// ---------------------------------------------------------------------------
__global__ __launch_bounds__(256) void k_xgemm(const float* __restrict__ x,
                                               const float* __restrict__ wih,
                                               const float* __restrict__ bih,
                                               const float* __restrict__ bhh) {
    __shared__ float As[16][132];  // [k][m]
    __shared__ float Ws[16][132];  // [k][n_local]

    int cell = blockIdx.y;
    int nb = blockIdx.x * 128;  // permuted column base
    const float* xa = x + (size_t)cell * (BB * DD);
    int tid = threadIdx.x;
    int tm = (tid >> 4) * 8;
    int tn = (tid & 15) * 8;

    float acc[8][8];
#pragma unroll
    for (int a = 0; a < 8; ++a)
#pragma unroll
        for (int b = 0; b < 8; ++b) acc[a][b] = 0.f;

    for (int kb = 0; kb < DD; kb += 16) {
        // load A chunk: 128 m x 16 k
#pragma unroll
        for (int it = 0; it < 2; ++it) {
            int idx = tid + it * 256;  // 0..511 float4
            int m = idx >> 2, kq = (idx & 3) * 4;
            float4 v = *reinterpret_cast<const float4*>(xa + m * DD + kb + kq);
            As[kq + 0][m] = v.x; As[kq + 1][m] = v.y;
            As[kq + 2][m] = v.z; As[kq + 3][m] = v.w;
        }
        // load W chunk: 128 permuted cols x 16 k
#pragma unroll
        for (int it = 0; it < 2; ++it) {
            int idx = tid + it * 256;
            int c = idx >> 2, kq = (idx & 3) * 4;
            int p = nb + c;
            int row = (p & 3) * 256 + (p >> 2);
            float4 v = *reinterpret_cast<const float4*>(wih + row * DD + kb + kq);
            Ws[kq + 0][c] = v.x; Ws[kq + 1][c] = v.y;
            Ws[kq + 2][c] = v.z; Ws[kq + 3][c] = v.w;
        }
        __syncthreads();
#pragma unroll 4
        for (int k = 0; k < 16; ++k) {
            float a[8], w[8];
#pragma unroll
            for (int u = 0; u < 2; ++u) {
                float4 va = *reinterpret_cast<const float4*>(&As[k][tm + u * 4]);
                a[u * 4 + 0] = va.x; a[u * 4 + 1] = va.y; a[u * 4 + 2] = va.z; a[u * 4 + 3] = va.w;
                float4 vw = *reinterpret_cast<const float4*>(&Ws[k][tn + u * 4]);
                w[u * 4 + 0] = vw.x; w[u * 4 + 1] = vw.y; w[u * 4 + 2] = vw.z; w[u * 4 + 3] = vw.w;
            }
#pragma unroll
            for (int mi = 0; mi < 8; ++mi)
#pragma unroll
                for (int ni = 0; ni < 8; ++ni) acc[mi][ni] += a[mi] * w[ni];
        }
        __syncthreads();
    }

    // epilogue: add fused biases (permuted), store
    float bsum[8];
#pragma unroll
    for (int ni = 0; ni < 8; ++ni) {
        int p = nb + tn + ni;
        int row = (p & 3) * 256 + (p >> 2);
        bsum[ni] = bih[row] + bhh[row];
    }
    float* xgp = g_xg + (size_t)cell * (BB * GG) + nb + tn;
#pragma unroll
    for (int mi = 0; mi < 8; ++mi) {
        float* dst = xgp + (size_t)(tm + mi) * GG;
#pragma unroll
        for (int nq = 0; nq < 2; ++nq) {
            float4 v;
            v.x = acc[mi][nq * 4 + 0] + bsum[nq * 4 + 0];
            v.y = acc[mi][nq * 4 + 1] + bsum[nq * 4 + 1];
            v.z = acc[mi][nq * 4 + 2] + bsum[nq * 4 + 2];
            v.w = acc[mi][nq * 4 + 3] + bsum[nq * 4 + 3];
            *reinterpret_cast<float4*>(dst + nq * 4) = v;
        }
    }
}

// ---------------------------------------------------------------------------
// Phase 2: one diagonal d. grid = (4 unit-slices, nd cells), 256 threads.
// CTA computes gates (M=128, 64 units x 4 gates = 256 permuted cols, K=256)
// then the LSTM nonlinearity fully in registers.
// ---------------------------------------------------------------------------
__global__ __launch_bounds__(256) void k_cell(int d, const float* __restrict__ whh) {
    __shared__ float As[16][132];  // [k][m]
    __shared__ float Ws[16][260];  // [k][c]

    int i = (d < 32 ? 0 : d - 31) + blockIdx.y;
    int j = d - i;
    int U = blockIdx.x;           // unit slice (64 units)
    int p = d & 1, q = p ^ 1;     // read parity / write parity

    const float* hrow = g_hrow + (p * 32 + i) * (BB * HH);
    const float* hcol = g_hcol + (p * 32 + j) * (BB * HH);

    int tid = threadIdx.x;
    int tm = (tid >> 4) * 8;      // 8 batch rows
    int tn = (tid & 15) * 16;     // 16 permuted cols = 4 units x 4 gates

    float acc[8][16];
    // init accumulators from precomputed xg (already includes both biases)
    const float* xgp = g_xg + (size_t)(i * 32 + j) * (BB * GG) + U * 256 + tn;
#pragma unroll
    for (int mi = 0; mi < 8; ++mi) {
        const float* src = xgp + (size_t)(tm + mi) * GG;
#pragma unroll
        for (int nq = 0; nq < 4; ++nq) {
            float4 v = *reinterpret_cast<const float4*>(src + nq * 4);
            acc[mi][nq * 4 + 0] = v.x; acc[mi][nq * 4 + 1] = v.y;
            acc[mi][nq * 4 + 2] = v.z; acc[mi][nq * 4 + 3] = v.w;
        }
    }

    for (int kb = 0; kb < 256; kb += 16) {
        const float* srcA = (kb < 128) ? (hrow + kb) : (hcol + (kb - 128));
        // load A chunk (h_cat slice): 128 m x 16 k
#pragma unroll
        for (int it = 0; it < 2; ++it) {
            int idx = tid + it * 256;
            int m = idx >> 2, kq = (idx & 3) * 4;
            float4 v = *reinterpret_cast<const float4*>(srcA + m * HH + kq);
            As[kq + 0][m] = v.x; As[kq + 1][m] = v.y;
            As[kq + 2][m] = v.z; As[kq + 3][m] = v.w;
        }
        // load W chunk: 256 permuted cols x 16 k
#pragma unroll
        for (int it = 0; it < 4; ++it) {
            int idx = tid + it * 256;
            int c = idx >> 2, kq = (idx & 3) * 4;
            int pg = U * 256 + c;
            int row = (pg & 3) * 256 + (pg >> 2);
            float4 v = *reinterpret_cast<const float4*>(whh + row * 256 + kb + kq);
            Ws[kq + 0][c] = v.x; Ws[kq + 1][c] = v.y;
            Ws[kq + 2][c] = v.z; Ws[kq + 3][c] = v.w;
        }
        __syncthreads();
#pragma unroll 4
        for (int k = 0; k < 16; ++k) {
            float a[8], w[16];
#pragma unroll
            for (int u = 0; u < 2; ++u) {
                float4 va = *reinterpret_cast<const float4*>(&As[k][tm + u * 4]);
                a[u * 4 + 0] = va.x; a[u * 4 + 1] = va.y; a[u * 4 + 2] = va.z; a[u * 4 + 3] = va.w;
            }
#pragma unroll
            for (int u = 0; u < 4; ++u) {
                float4 vw = *reinterpret_cast<const float4*>(&Ws[k][tn + u * 4]);
                w[u * 4 + 0] = vw.x; w[u * 4 + 1] = vw.y; w[u * 4 + 2] = vw.z; w[u * 4 + 3] = vw.w;
            }
#pragma unroll
            for (int mi = 0; mi < 8; ++mi)
#pragma unroll
                for (int ni = 0; ni < 16; ++ni) acc[mi][ni] += a[mi] * w[ni];
        }
        __syncthreads();
    }

    // LSTM nonlinearity, in registers. Units 0..127 -> row carry, 128..255 -> col carry.
    bool isrow = (U < 2);
    const float* csrc;
    float* hdst;
    float* cdst;
    if (isrow) {
        csrc = g_crow + (p * 32 + i) * (BB * HH);
        hdst = g_hrow + (q * 32 + i) * (BB * HH);
        cdst = g_crow + (q * 32 + i) * (BB * HH);
    } else {
        csrc = g_ccol + (p * 32 + j) * (BB * HH);
        hdst = g_hcol + (q * 32 + j) * (BB * HH);
        cdst = g_ccol + (q * 32 + j) * (BB * HH);
    }
    int ub = (U & 1) * 64 + (tn >> 2);  // column base within the 128-wide buffer

#pragma unroll
    for (int mi = 0; mi < 8; ++mi) {
        int m = tm + mi;
#pragma unroll
        for (int u2 = 0; u2 < 4; ++u2) {
            float gi = acc[mi][u2 * 4 + 0];
            float gf = acc[mi][u2 * 4 + 1];
            float gg = acc[mi][u2 * 4 + 2];
            float go = acc[mi][u2 * 4 + 3];
            float co = csrc[m * HH + ub + u2];
            float cn = sigm(gf) * co + sigm(gi) * tanhf(gg);
            float hn = sigm(go) * tanhf(cn);
            hdst[m * HH + ub + u2] = hn;
            cdst[m * HH + ub + u2] = cn;
        }
    }
}

// ---------------------------------------------------------------------------
// Pack output: h2 = [h_row_final[31], h_col_final[31]], c2 likewise.
// Final write parity after d=62 is 1. out = [h2 (128x256), c2 (128x256)].
// ---------------------------------------------------------------------------
__global__ void k_out(float* __restrict__ out, int out_size) {
    int t = blockIdx.x * blockDim.x + threadIdx.x;
    if (t >= out_size) return;
    int sel = t >> 15;        // 0 = h, 1 = c
    int r = t & 32767;
    int m = r >> 8;
    int u = r & 255;
    const float* base;
    if (u < HH)
        base = (sel ? g_crow : g_hrow) + (1 * 32 + 31) * (BB * HH) + m * HH + u;
    else
        base = (sel ? g_ccol : g_hcol) + (1 * 32 + 31) * (BB * HH) + m * HH + (u - HH);
    out[t] = *base;
}

// ---------------------------------------------------------------------------
extern "C" void kernel_launch(void* const* d_in, const int* in_sizes, int n_in,
                              void* d_out, int out_size) {
    const float* x   = (const float*)d_in[0];
    const float* wih = (const float*)d_in[1];
    const float* whh = (const float*)d_in[2];
    const float* bih = (const float*)d_in[3];
    const float* bhh = (const float*)d_in[4];

    k_zero<<<1024, 256>>>();
    k_xgemm<<<dim3(8, 1024), 256>>>(x, wih, bih, bhh);
    for (int d = 0; d < 63; ++d) {
        int nd = (d < 32) ? (d + 1) : (63 - d);
        k_cell<<<dim3(4, nd), 256>>>(d, whh);
    }
    k_out<<<(out_size + 255) / 256, 256>>>((float*)d_out, out_size);
}

// round 3
// speedup vs baseline: 3.0021x; 3.0021x over previous
#include <cuda_runtime.h>
#include <cuda_bf16.h>
#include <cstdint>
#include <math.h>

#define BB 128
#define HH 128
#define KK 384
#define NCELL 1024

typedef __nv_bfloat16 bf16;

// ---- device scratch (allocation-free) ----
__device__ bf16  g_whi[1024 * KK];               // permuted weights hi [p][k]
__device__ bf16  g_wlo[1024 * KK];               // permuted weights lo
__device__ float g_biasp[1024];                  // permuted b_ih+b_hh
__device__ bf16  g_xhi[(size_t)NCELL * BB * 128];  // x hi [cell][m][d]
__device__ bf16  g_xlo[(size_t)NCELL * BB * 128];
// h carries (bf16 hi/lo) and c carries (f32), double-buffered by parity
__device__ bf16  g_hrh[2 * 32 * BB * HH], g_hrl[2 * 32 * BB * HH];
__device__ bf16  g_hch[2 * 32 * BB * HH], g_hcl[2 * 32 * BB * HH];
__device__ float g_crow[2 * 32 * BB * HH], g_ccol[2 * 32 * BB * HH];

// ---- PTX helpers (portable sm_80+ subset, works on sm_100) ----
__device__ __forceinline__ uint32_t smem_u32(const void* p) {
    uint32_t a;
    asm("{ .reg .u64 t; cvta.to.shared.u64 t, %1; cvt.u32.u64 %0, t; }" : "=r"(a) : "l"(p));
    return a;
}
#define CP16(smem, gptr) \
    asm volatile("cp.async.cg.shared.global [%0], [%1], 16;" :: "r"(smem), "l"(gptr))
#define CP_COMMIT() asm volatile("cp.async.commit_group;" ::: "memory")
#define CP_WAIT1() asm volatile("cp.async.wait_group 1;" ::: "memory")
#define CP_WAIT0() asm volatile("cp.async.wait_group 0;" ::: "memory")
#define LDSM4(r, addr) \
    asm volatile("ldmatrix.sync.aligned.m8n8.x4.shared.b16 {%0,%1,%2,%3}, [%4];" \
                 : "=r"((r)[0]), "=r"((r)[1]), "=r"((r)[2]), "=r"((r)[3]) : "r"(addr))
#define MMA(d, a, b0, b1) \
    asm volatile("mma.sync.aligned.m16n8k16.row.col.f32.bf16.bf16.f32 " \
                 "{%0,%1,%2,%3},{%4,%5,%6,%7},{%8,%9},{%0,%1,%2,%3};" \
                 : "+f"((d)[0]), "+f"((d)[1]), "+f"((d)[2]), "+f"((d)[3]) \
                 : "r"((a)[0]), "r"((a)[1]), "r"((a)[2]), "r"((a)[3]), "r"(b0), "r"(b1))

__device__ __forceinline__ float sigm_f(float x) {
    return __fdividef(1.0f, 1.0f + __expf(-x));
}
__device__ __forceinline__ float tanh_f(float x) {
    return fmaf(2.0f, sigm_f(2.0f * x), -1.0f);
}

// permuted col p -> original gate row: G=p>>5, r5=p&31, gate=r5>>3, w=r5&7
__device__ __forceinline__ int grow_of(int p) {
    int G = p >> 5, r5 = p & 31;
    return (r5 >> 3) * 256 + G * 8 + (r5 & 7);
}

// ---------------------------------------------------------------------------
__global__ void k_prep_w(const float* __restrict__ wih, const float* __restrict__ whh,
                         const float* __restrict__ bih, const float* __restrict__ bhh) {
    int t = blockIdx.x * blockDim.x + threadIdx.x;
    if (t >= 1024 * KK) return;
    int p = t / KK, k = t % KK;
    int gr = grow_of(p);
    float v = (k < 128) ? wih[gr * 128 + k] : whh[gr * 256 + (k - 128)];
    bf16 hi = __float2bfloat16(v);
    g_whi[t] = hi;
    g_wlo[t] = __float2bfloat16(v - __bfloat162float(hi));
    if (k == 0) g_biasp[p] = bih[gr] + bhh[gr];
}

__global__ void k_prep_x(const float* __restrict__ x) {
    size_t t = (size_t)blockIdx.x * blockDim.x + threadIdx.x;
    if (t >= (size_t)NCELL * BB * 128) return;
    float v = x[t];
    bf16 hi = __float2bfloat16(v);
    g_xhi[t] = hi;
    g_xlo[t] = __float2bfloat16(v - __bfloat162float(hi));
}

__global__ void k_zero() {
    int t = blockIdx.x * blockDim.x + threadIdx.x;
    uint4 z = make_uint4(0, 0, 0, 0);
    if (t < 2 * 32 * BB * HH * 2 / 16) {  // bf16 arrays: 2MB each / 16B
        reinterpret_cast<uint4*>(g_hrh)[t] = z;
        reinterpret_cast<uint4*>(g_hrl)[t] = z;
        reinterpret_cast<uint4*>(g_hch)[t] = z;
        reinterpret_cast<uint4*>(g_hcl)[t] = z;
        reinterpret_cast<uint4*>(g_crow)[2 * t] = z;      // f32 arrays are 2x bytes
        reinterpret_cast<uint4*>(g_crow)[2 * t + 1] = z;
        reinterpret_cast<uint4*>(g_ccol)[2 * t] = z;
        reinterpret_cast<uint4*>(g_ccol)[2 * t + 1] = z;
    }
}

// ---------------------------------------------------------------------------
// One diagonal: grid=(8 unit-slices, nd cells), 256 threads (8 warps, 4x2).
// gates[128m x 128p] = [x | h_row | h_col](128x384) @ Wperm^T via bf16 split
// mma.sync (3 products: hh, hl, lh), cp.async double-buffered pipeline.
// ---------------------------------------------------------------------------
#define PITCH 80
#define MATB (128 * PITCH)   // 10240 bytes per matrix buffer
#define STAGEB (4 * MATB)    // A_hi, A_lo, B_hi, B_lo
#define SMEM_TOTAL (2 * STAGEB + 512)

__global__ __launch_bounds__(256) void k_cell(int dd) {
    extern __shared__ char smem[];
    uint32_t sb = smem_u32(smem);
    int tid = threadIdx.x, lane = tid & 31, w = tid >> 5;
    int mw = w & 3, nw = w >> 2;

    int i = (dd < 32 ? 0 : dd - 31) + blockIdx.y;
    int j = dd - i;
    int U = blockIdx.x;
    int par = dd & 1, qar = par ^ 1;
    int cell = i * 32 + j;

    const bf16* xh = g_xhi + (size_t)cell * BB * 128;
    const bf16* xl = g_xlo + (size_t)cell * BB * 128;
    const bf16* hrh = g_hrh + (par * 32 + i) * (BB * HH);
    const bf16* hrl = g_hrl + (par * 32 + i) * (BB * HH);
    const bf16* hch = g_hch + (par * 32 + j) * (BB * HH);
    const bf16* hcl = g_hcl + (par * 32 + j) * (BB * HH);

    // bias cache
    if (tid < 128)
        reinterpret_cast<float*>(smem + 2 * STAGEB)[tid] = g_biasp[U * 128 + tid];

    int lr = tid >> 1;            // row 0..127
    int lq = (tid & 1) * 2;       // first 16B-quad (of 4 per 64B row)
    uint32_t so = (uint32_t)lr * PITCH + lq * 16;
    const bf16* bhp = g_whi + (size_t)(U * 128 + lr) * KK;
    const bf16* blp = g_wlo + (size_t)(U * 128 + lr) * KK;

    auto ld_chunk = [&](int kb, int s) {
        uint32_t st = sb + s * STAGEB;
        const bf16 *ah, *al;
        if (kb < 4)      { ah = xh  + lr * 128 + kb * 32;        al = xl  + lr * 128 + kb * 32; }
        else if (kb < 8) { ah = hrh + lr * 128 + (kb - 4) * 32;  al = hrl + lr * 128 + (kb - 4) * 32; }
        else             { ah = hch + lr * 128 + (kb - 8) * 32;  al = hcl + lr * 128 + (kb - 8) * 32; }
        CP16(st + so,            ah + lq * 8);
        CP16(st + so + 16,       ah + lq * 8 + 8);
        CP16(st + MATB + so,     al + lq * 8);
        CP16(st + MATB + so + 16, al + lq * 8 + 8);
        const bf16* bh = bhp + kb * 32;
        const bf16* bl = blp + kb * 32;
        CP16(st + 2 * MATB + so,      bh + lq * 8);
        CP16(st + 2 * MATB + so + 16, bh + lq * 8 + 8);
        CP16(st + 3 * MATB + so,      bl + lq * 8);
        CP16(st + 3 * MATB + so + 16, bl + lq * 8 + 8);
    };

    float acc[2][8][4];
#pragma unroll
    for (int a = 0; a < 2; ++a)
#pragma unroll
        for (int b = 0; b < 8; ++b)
#pragma unroll
            for (int c = 0; c < 4; ++c) acc[a][b][c] = 0.f;

    ld_chunk(0, 0);
    CP_COMMIT();

    // lane addressing for ldmatrix
    uint32_t a_off = (uint32_t)(lane & 15) * PITCH + ((lane >> 4) << 4);
    uint32_t b_row = (uint32_t)((lane & 7) + ((lane >> 4) << 3));
    uint32_t b_off = b_row * PITCH + (((lane >> 3) & 1) << 4);

    for (int kb = 0; kb < 12; ++kb) {
        int s = kb & 1;
        if (kb < 11) { ld_chunk(kb + 1, s ^ 1); CP_COMMIT(); CP_WAIT1(); }
        else         { CP_WAIT0(); }
        __syncthreads();
        uint32_t st = sb + s * STAGEB;
#pragma unroll
        for (int ks = 0; ks < 2; ++ks) {
            uint32_t ahi[2][4], alo[2][4];
#pragma unroll
            for (int mt = 0; mt < 2; ++mt) {
                uint32_t aa = st + (uint32_t)(mw * 32 + mt * 16) * PITCH + ks * 32 + a_off;
                LDSM4(ahi[mt], aa);
                LDSM4(alo[mt], aa + MATB);
            }
            uint32_t bhi[4][4], blo[4][4];
#pragma unroll
            for (int bt = 0; bt < 4; ++bt) {
                uint32_t ba = st + 2 * MATB + (uint32_t)(nw * 64 + bt * 16) * PITCH + ks * 32 + b_off;
                LDSM4(bhi[bt], ba);
                LDSM4(blo[bt], ba + MATB);
            }
#pragma unroll
            for (int mt = 0; mt < 2; ++mt)
#pragma unroll
                for (int f = 0; f < 8; ++f) {
                    int bt = f >> 1, hf = (f & 1) * 2;
                    MMA(acc[mt][f], ahi[mt], bhi[bt][hf], bhi[bt][hf + 1]);
                    MMA(acc[mt][f], ahi[mt], blo[bt][hf], blo[bt][hf + 1]);
                    MMA(acc[mt][f], alo[mt], bhi[bt][hf], bhi[bt][hf + 1]);
                }
        }
        __syncthreads();
    }

    // ---- epilogue: full (i,f,g,o) quadruples live in-thread by construction
    const float* bias_s = reinterpret_cast<const float*>(smem + 2 * STAGEB);
    bool isrow = (U < 4);
    int ub = (U & 3) * 32;
    const float* csrc;
    float* cdst;
    bf16 *hdh, *hdl;
    if (isrow) {
        csrc = g_crow + (par * 32 + i) * (BB * HH);
        cdst = g_crow + (qar * 32 + i) * (BB * HH);
        hdh = g_hrh + (qar * 32 + i) * (BB * HH);
        hdl = g_hrl + (qar * 32 + i) * (BB * HH);
    } else {
        csrc = g_ccol + (par * 32 + j) * (BB * HH);
        cdst = g_ccol + (qar * 32 + j) * (BB * HH);
        hdh = g_hch + (qar * 32 + j) * (BB * HH);
        hdl = g_hcl + (qar * 32 + j) * (BB * HH);
    }

#pragma unroll
    for (int mt = 0; mt < 2; ++mt) {
        int m0 = mw * 32 + mt * 16 + (lane >> 2);
#pragma unroll
        for (int dr = 0; dr < 2; ++dr) {
            int m = m0 + dr * 8;
#pragma unroll
            for (int gi = 0; gi < 2; ++gi) {
#pragma unroll
                for (int du = 0; du < 2; ++du) {
                    int e = dr * 2 + du;
                    int wslot = (lane & 3) * 2 + du;
                    int ul = (nw * 2 + gi) * 8 + wslot;        // unit_local 0..31
                    int pb = nw * 64 + gi * 32 + wslot;        // p_local base (gate 0)
                    float I = acc[mt][gi * 4 + 0][e] + bias_s[pb];
                    float F = acc[mt][gi * 4 + 1][e] + bias_s[pb + 8];
                    float G = acc[mt][gi * 4 + 2][e] + bias_s[pb + 16];
                    float O = acc[mt][gi * 4 + 3][e] + bias_s[pb + 24];
                    int idx = m * HH + ub + ul;
                    float cold = csrc[idx];
                    float cn = sigm_f(F) * cold + sigm_f(I) * tanh_f(G);
                    float hn = sigm_f(O) * tanh_f(cn);
                    cdst[idx] = cn;
                    bf16 hh2 = __float2bfloat16(hn);
                    hdh[idx] = hh2;
                    hdl[idx] = __float2bfloat16(hn - __bfloat162float(hh2));
                }
            }
        }
    }
}

// ---------------------------------------------------------------------------
__global__ void k_out(float* __restrict__ out, int out_size) {
    int t = blockIdx.x * blockDim.x + threadIdx.x;
    if (t >= out_size) return;
    int sel = t >> 15;        // 0=h, 1=c
    int r = t & 32767;
    int m = r >> 8;
    int u = r & 255;
    int base = (32 + 31) * (BB * HH);   // parity 1, line 31
    float v;
    if (u < HH) {
        int idx = base + m * HH + u;
        v = sel ? g_crow[idx]
                : (__bfloat162float(g_hrh[idx]) + __bfloat162float(g_hrl[idx]));
    } else {
        int idx = base + m * HH + (u - HH);
        v = sel ? g_ccol[idx]
                : (__bfloat162float(g_hch[idx]) + __bfloat162float(g_hcl[idx]));
    }
    out[t] = v;
}

// ---------------------------------------------------------------------------
extern "C" void kernel_launch(void* const* d_in, const int* in_sizes, int n_in,
                              void* d_out, int out_size) {
    const float* x   = (const float*)d_in[0];
    const float* wih = (const float*)d_in[1];
    const float* whh = (const float*)d_in[2];
    const float* bih = (const float*)d_in[3];
    const float* bhh = (const float*)d_in[4];

    cudaFuncSetAttribute(k_cell, cudaFuncAttributeMaxDynamicSharedMemorySize, SMEM_TOTAL);

    k_zero<<<1024, 256>>>();
    k_prep_w<<<(1024 * KK + 255) / 256, 256>>>(wih, whh, bih, bhh);
    k_prep_x<<<(int)(((size_t)NCELL * BB * 128 + 255) / 256), 256>>>(x);
    for (int d = 0; d < 63; ++d) {
        int nd = (d < 32) ? (d + 1) : (63 - d);
        k_cell<<<dim3(8, nd), 256, SMEM_TOTAL>>>(d);
    }
    k_out<<<(out_size + 255) / 256, 256>>>((float*)d_out, out_size);
}

// round 5
// speedup vs baseline: 3.0418x; 1.0132x over previous
#include <cuda_runtime.h>
#include <cuda_bf16.h>
#include <cstdint>
#include <math.h>

#define BB 128
#define HH 128
#define KK 384
#define NCELL 1024

typedef __nv_bfloat16 bf16;

// ---- device scratch (allocation-free) ----
__device__ bf16  g_whi[1024 * KK];               // permuted weights hi [p][k]
__device__ bf16  g_wlo[1024 * KK];               // permuted weights lo
__device__ float g_biasp[1024];                  // permuted b_ih+b_hh
__device__ bf16  g_xhi[(size_t)NCELL * BB * 128];  // x hi [cell][m][d]
__device__ bf16  g_xlo[(size_t)NCELL * BB * 128];
// h carries (bf16 hi/lo) and c carries (f32), double-buffered by parity
__device__ bf16  g_hrh[2 * 32 * BB * HH], g_hrl[2 * 32 * BB * HH];
__device__ bf16  g_hch[2 * 32 * BB * HH], g_hcl[2 * 32 * BB * HH];
__device__ float g_crow[2 * 32 * BB * HH], g_ccol[2 * 32 * BB * HH];

// ---- PTX helpers (portable sm_80+ subset, works on sm_100) ----
__device__ __forceinline__ uint32_t smem_u32(const void* p) {
    uint32_t a;
    asm("{ .reg .u64 t; cvta.to.shared.u64 t, %1; cvt.u32.u64 %0, t; }" : "=r"(a) : "l"(p));
    return a;
}
#define CP16(smem, gptr) \
    asm volatile("cp.async.cg.shared.global [%0], [%1], 16;" :: "r"(smem), "l"(gptr))
#define CP_COMMIT() asm volatile("cp.async.commit_group;" ::: "memory")
#define CP_WAIT2() asm volatile("cp.async.wait_group 2;" ::: "memory")
#define CP_WAIT0() asm volatile("cp.async.wait_group 0;" ::: "memory")
#define LDSM4(r, addr) \
    asm volatile("ldmatrix.sync.aligned.m8n8.x4.shared.b16 {%0,%1,%2,%3}, [%4];" \
                 : "=r"((r)[0]), "=r"((r)[1]), "=r"((r)[2]), "=r"((r)[3]) : "r"(addr))
#define MMA(d, a, b0, b1) \
    asm volatile("mma.sync.aligned.m16n8k16.row.col.f32.bf16.bf16.f32 " \
                 "{%0,%1,%2,%3},{%4,%5,%6,%7},{%8,%9},{%0,%1,%2,%3};" \
                 : "+f"((d)[0]), "+f"((d)[1]), "+f"((d)[2]), "+f"((d)[3]) \
                 : "r"((a)[0]), "r"((a)[1]), "r"((a)[2]), "r"((a)[3]), "r"(b0), "r"(b1))

__device__ __forceinline__ float sigm_f(float x) {
    return __fdividef(1.0f, 1.0f + __expf(-x));
}
__device__ __forceinline__ float tanh_f(float x) {
    return fmaf(2.0f, sigm_f(2.0f * x), -1.0f);
}

// permuted col p -> original gate row: G=p>>5, r5=p&31, gate=r5>>3, w=r5&7
__device__ __forceinline__ int grow_of(int p) {
    int G = p >> 5, r5 = p & 31;
    return (r5 >> 3) * 256 + G * 8 + (r5 & 7);
}

// ---------------------------------------------------------------------------
__global__ void k_prep_w(const float* __restrict__ wih, const float* __restrict__ whh,
                         const float* __restrict__ bih, const float* __restrict__ bhh) {
    int t = blockIdx.x * blockDim.x + threadIdx.x;
    if (t >= 1024 * KK) return;
    int p = t / KK, k = t % KK;
    int gr = grow_of(p);
    float v = (k < 128) ? wih[gr * 128 + k] : whh[gr * 256 + (k - 128)];
    bf16 hi = __float2bfloat16(v);
    g_whi[t] = hi;
    g_wlo[t] = __float2bfloat16(v - __bfloat162float(hi));
    if (k == 0) g_biasp[p] = bih[gr] + bhh[gr];
}

__global__ void k_prep_x(const float* __restrict__ x) {
    size_t t = (size_t)blockIdx.x * blockDim.x + threadIdx.x;
    if (t >= (size_t)NCELL * BB * 128) return;
    float v = x[t];
    bf16 hi = __float2bfloat16(v);
    g_xhi[t] = hi;
    g_xlo[t] = __float2bfloat16(v - __bfloat162float(hi));
}

__global__ void k_zero() {
    int t = blockIdx.x * blockDim.x + threadIdx.x;
    uint4 z = make_uint4(0, 0, 0, 0);
    if (t < 2 * 32 * BB * HH * 2 / 16) {  // bf16 arrays: 2MB each / 16B
        reinterpret_cast<uint4*>(g_hrh)[t] = z;
        reinterpret_cast<uint4*>(g_hrl)[t] = z;
        reinterpret_cast<uint4*>(g_hch)[t] = z;
        reinterpret_cast<uint4*>(g_hcl)[t] = z;
        reinterpret_cast<uint4*>(g_crow)[2 * t] = z;
        reinterpret_cast<uint4*>(g_crow)[2 * t + 1] = z;
        reinterpret_cast<uint4*>(g_ccol)[2 * t] = z;
        reinterpret_cast<uint4*>(g_ccol)[2 * t + 1] = z;
    }
}

// ---------------------------------------------------------------------------
// One diagonal: grid=(8 unit-slices, nd cells), 256 threads (8 warps, 4x2).
// gates[128m x 128p] = [x | h_row | h_col](128x384) @ Wperm^T via bf16 split
// mma.sync (3 products: hh, hl, lh). 4-stage cp.async pipeline, prefetch
// distance 3, single __syncthreads per iteration.
// ---------------------------------------------------------------------------
#define PITCH 80
#define MATB (128 * PITCH)   // 10240 bytes per matrix buffer
#define STAGEB (4 * MATB)    // A_hi, A_lo, B_hi, B_lo
#define NSTAGE 4
#define SMEM_TOTAL (NSTAGE * STAGEB + 512)

__global__ __launch_bounds__(256) void k_cell(int dd) {
    extern __shared__ char smem[];
    uint32_t sb = smem_u32(smem);
    int tid = threadIdx.x, lane = tid & 31, w = tid >> 5;
    int mw = w & 3, nw = w >> 2;

    int i = (dd < 32 ? 0 : dd - 31) + blockIdx.y;
    int j = dd - i;
    int U = blockIdx.x;
    int par = dd & 1, qar = par ^ 1;
    int cell = i * 32 + j;

    const bf16* xh = g_xhi + (size_t)cell * BB * 128;
    const bf16* xl = g_xlo + (size_t)cell * BB * 128;
    const bf16* hrh = g_hrh + (par * 32 + i) * (BB * HH);
    const bf16* hrl = g_hrl + (par * 32 + i) * (BB * HH);
    const bf16* hch = g_hch + (par * 32 + j) * (BB * HH);
    const bf16* hcl = g_hcl + (par * 32 + j) * (BB * HH);

    // bias cache
    if (tid < 128)
        reinterpret_cast<float*>(smem + NSTAGE * STAGEB)[tid] = g_biasp[U * 128 + tid];

    int lr = tid >> 1;            // row 0..127
    int lq = (tid & 1) * 2;       // first 16B-quad (of 4 per 64B row)
    uint32_t so = (uint32_t)lr * PITCH + lq * 16;
    const bf16* bhp = g_whi + (size_t)(U * 128 + lr) * KK;
    const bf16* blp = g_wlo + (size_t)(U * 128 + lr) * KK;

    auto ld_chunk = [&](int kb, int s) {
        uint32_t st = sb + s * STAGEB;
        const bf16 *ah, *al;
        if (kb < 4)      { ah = xh  + lr * 128 + kb * 32;        al = xl  + lr * 128 + kb * 32; }
        else if (kb < 8) { ah = hrh + lr * 128 + (kb - 4) * 32;  al = hrl + lr * 128 + (kb - 4) * 32; }
        else             { ah = hch + lr * 128 + (kb - 8) * 32;  al = hcl + lr * 128 + (kb - 8) * 32; }
        CP16(st + so,             ah + lq * 8);
        CP16(st + so + 16,        ah + lq * 8 + 8);
        CP16(st + MATB + so,      al + lq * 8);
        CP16(st + MATB + so + 16, al + lq * 8 + 8);
        const bf16* bh = bhp + kb * 32;
        const bf16* bl = blp + kb * 32;
        CP16(st + 2 * MATB + so,      bh + lq * 8);
        CP16(st + 2 * MATB + so + 16, bh + lq * 8 + 8);
        CP16(st + 3 * MATB + so,      bl + lq * 8);
        CP16(st + 3 * MATB + so + 16, bl + lq * 8 + 8);
    };

    float acc[2][8][4];
#pragma unroll
    for (int a = 0; a < 2; ++a)
#pragma unroll
        for (int b = 0; b < 8; ++b)
#pragma unroll
            for (int c = 0; c < 4; ++c) acc[a][b][c] = 0.f;

    // preload chunks 0..2 into stages 0..2
    ld_chunk(0, 0); CP_COMMIT();
    ld_chunk(1, 1); CP_COMMIT();
    ld_chunk(2, 2); CP_COMMIT();

    // lane addressing for ldmatrix
    uint32_t a_off = (uint32_t)(lane & 15) * PITCH + ((lane >> 4) << 4);
    uint32_t b_row = (uint32_t)((lane & 7) + ((lane >> 4) << 3));
    uint32_t b_off = b_row * PITCH + (((lane >> 3) & 1) << 4);

    for (int kb = 0; kb < 12; ++kb) {
        int s = kb & 3;
        if (kb < 9) CP_WAIT2();   // chunk kb landed (pending kb+1,kb+2)
        else        CP_WAIT0();
        __syncthreads();          // data visible + stage (kb-1)&3 free for overwrite
        if (kb < 9) { ld_chunk(kb + 3, (kb + 3) & 3); CP_COMMIT(); }
        uint32_t st = sb + s * STAGEB;
#pragma unroll
        for (int ks = 0; ks < 2; ++ks) {
            uint32_t ahi[2][4], alo[2][4];
#pragma unroll
            for (int mt = 0; mt < 2; ++mt) {
                uint32_t aa = st + (uint32_t)(mw * 32 + mt * 16) * PITCH + ks * 32 + a_off;
                LDSM4(ahi[mt], aa);
                LDSM4(alo[mt], aa + MATB);
            }
            uint32_t bhi[4][4], blo[4][4];
#pragma unroll
            for (int bt = 0; bt < 4; ++bt) {
                uint32_t ba = st + 2 * MATB + (uint32_t)(nw * 64 + bt * 16) * PITCH + ks * 32 + b_off;
                LDSM4(bhi[bt], ba);
                LDSM4(blo[bt], ba + MATB);
            }
#pragma unroll
            for (int mt = 0; mt < 2; ++mt)
#pragma unroll
                for (int f = 0; f < 8; ++f) {
                    int bt = f >> 1, hf = (f & 1) * 2;
                    MMA(acc[mt][f], ahi[mt], bhi[bt][hf], bhi[bt][hf + 1]);
                    MMA(acc[mt][f], ahi[mt], blo[bt][hf], blo[bt][hf + 1]);
                    MMA(acc[mt][f], alo[mt], bhi[bt][hf], bhi[bt][hf + 1]);
                }
        }
    }

    // ---- epilogue: full (i,f,g,o) quadruples live in-thread by construction
    const float* bias_s = reinterpret_cast<const float*>(smem + NSTAGE * STAGEB);
    bool isrow = (U < 4);
    int ub = (U & 3) * 32;
    const float* csrc;
    float* cdst;
    bf16 *hdh, *hdl;
    if (isrow) {
        csrc = g_crow + (par * 32 + i) * (BB * HH);
        cdst = g_crow + (qar * 32 + i) * (BB * HH);
        hdh = g_hrh + (qar * 32 + i) * (BB * HH);
        hdl = g_hrl + (qar * 32 + i) * (BB * HH);
    } else {
        csrc = g_ccol + (par * 32 + j) * (BB * HH);
        cdst = g_ccol + (qar * 32 + j) * (BB * HH);
        hdh = g_hch + (qar * 32 + j) * (BB * HH);
        hdl = g_hcl + (qar * 32 + j) * (BB * HH);
    }

#pragma unroll
    for (int mt = 0; mt < 2; ++mt) {
        int m0 = mw * 32 + mt * 16 + (lane >> 2);
#pragma unroll
        for (int dr = 0; dr < 2; ++dr) {
            int m = m0 + dr * 8;
#pragma unroll
            for (int gi = 0; gi < 2; ++gi) {
#pragma unroll
                for (int du = 0; du < 2; ++du) {
                    int e = dr * 2 + du;
                    int wslot = (lane & 3) * 2 + du;
                    int ul = (nw * 2 + gi) * 8 + wslot;        // unit_local 0..31
                    int pb = nw * 64 + gi * 32 + wslot;        // p_local base (gate 0)
                    float I = acc[mt][gi * 4 + 0][e] + bias_s[pb];
                    float F = acc[mt][gi * 4 + 1][e] + bias_s[pb + 8];
                    float G = acc[mt][gi * 4 + 2][e] + bias_s[pb + 16];
                    float O = acc[mt][gi * 4 + 3][e] + bias_s[pb + 24];
                    int idx = m * HH + ub + ul;
                    float cold = csrc[idx];
                    float cn = sigm_f(F) * cold + sigm_f(I) * tanh_f(G);
                    float hn = sigm_f(O) * tanh_f(cn);
                    cdst[idx] = cn;
                    bf16 hh2 = __float2bfloat16(hn);
                    hdh[idx] = hh2;
                    hdl[idx] = __float2bfloat16(hn - __bfloat162float(hh2));
                }
            }
        }
    }
}

// ---------------------------------------------------------------------------
__global__ void k_out(float* __restrict__ out, int out_size) {
    int t = blockIdx.x * blockDim.x + threadIdx.x;
    if (t >= out_size) return;
    int sel = t >> 15;        // 0=h, 1=c
    int r = t & 32767;
    int m = r >> 8;
    int u = r & 255;
    int base = (32 + 31) * (BB * HH);   // parity 1, line 31
    float v;
    if (u < HH) {
        int idx = base + m * HH + u;
        v = sel ? g_crow[idx]
                : (__bfloat162float(g_hrh[idx]) + __bfloat162float(g_hrl[idx]));
    } else {
        int idx = base + m * HH + (u - HH);
        v = sel ? g_ccol[idx]
                : (__bfloat162float(g_hch[idx]) + __bfloat162float(g_hcl[idx]));
    }
    out[t] = v;
}

// ---------------------------------------------------------------------------
extern "C" void kernel_launch(void* const* d_in, const int* in_sizes, int n_in,
                              void* d_out, int out_size) {
    const float* x   = (const float*)d_in[0];
    const float* wih = (const float*)d_in[1];
    const float* whh = (const float*)d_in[2];
    const float* bih = (const float*)d_in[3];
    const float* bhh = (const float*)d_in[4];

    cudaFuncSetAttribute(k_cell, cudaFuncAttributeMaxDynamicSharedMemorySize, SMEM_TOTAL);

    k_zero<<<1024, 256>>>();
    k_prep_w<<<(1024 * KK + 255) / 256, 256>>>(wih, whh, bih, bhh);
    k_prep_x<<<(int)(((size_t)NCELL * BB * 128 + 255) / 256), 256>>>(x);
    for (int d = 0; d < 63; ++d) {
        int nd = (d < 32) ? (d + 1) : (63 - d);
        k_cell<<<dim3(8, nd), 256, SMEM_TOTAL>>>(d);
    }
    k_out<<<(out_size + 255) / 256, 256>>>((float*)d_out, out_size);
}

// round 6
// speedup vs baseline: 4.0882x; 1.3440x over previous
#include <cuda_runtime.h>
#include <cuda_bf16.h>
#include <cstdint>
#include <math.h>

#define BB 128
#define HH 128
#define KK 384
#define NCELL 1024

typedef __nv_bfloat16 bf16;

// ---- device scratch (allocation-free) ----
__device__ bf16  g_whi[1024 * KK];               // permuted weights hi [p][k]
__device__ bf16  g_wlo[1024 * KK];               // permuted weights lo
__device__ float g_biasp[1024];                  // permuted b_ih+b_hh
__device__ bf16  g_xhi[(size_t)NCELL * BB * 128];  // x hi [cell][m][d]
__device__ bf16  g_xlo[(size_t)NCELL * BB * 128];
// h carries (bf16 hi/lo) and c carries (f32), double-buffered by parity
__device__ bf16  g_hrh[2 * 32 * BB * HH], g_hrl[2 * 32 * BB * HH];
__device__ bf16  g_hch[2 * 32 * BB * HH], g_hcl[2 * 32 * BB * HH];
__device__ float g_crow[2 * 32 * BB * HH], g_ccol[2 * 32 * BB * HH];

// ---- PTX helpers (portable sm_80+ subset, works on sm_100) ----
__device__ __forceinline__ uint32_t smem_u32(const void* p) {
    uint32_t a;
    asm("{ .reg .u64 t; cvta.to.shared.u64 t, %1; cvt.u32.u64 %0, t; }" : "=r"(a) : "l"(p));
    return a;
}
#define CP16(smem, gptr) \
    asm volatile("cp.async.cg.shared.global [%0], [%1], 16;" :: "r"(smem), "l"(gptr))
#define CP_COMMIT() asm volatile("cp.async.commit_group;" ::: "memory")
#define CP_WAIT1() asm volatile("cp.async.wait_group 1;" ::: "memory")
#define CP_WAIT0() asm volatile("cp.async.wait_group 0;" ::: "memory")
#define LDSM4(r, addr) \
    asm volatile("ldmatrix.sync.aligned.m8n8.x4.shared.b16 {%0,%1,%2,%3}, [%4];" \
                 : "=r"((r)[0]), "=r"((r)[1]), "=r"((r)[2]), "=r"((r)[3]) : "r"(addr))
#define MMA(d, a, b0, b1) \
    asm volatile("mma.sync.aligned.m16n8k16.row.col.f32.bf16.bf16.f32 " \
                 "{%0,%1,%2,%3},{%4,%5,%6,%7},{%8,%9},{%0,%1,%2,%3};" \
                 : "+f"((d)[0]), "+f"((d)[1]), "+f"((d)[2]), "+f"((d)[3]) \
                 : "r"((a)[0]), "r"((a)[1]), "r"((a)[2]), "r"((a)[3]), "r"(b0), "r"(b1))

__device__ __forceinline__ float sigm_f(float x) {
    return __fdividef(1.0f, 1.0f + __expf(-x));
}
__device__ __forceinline__ float tanh_f(float x) {
    return fmaf(2.0f, sigm_f(2.0f * x), -1.0f);
}

// permuted col p -> original gate row: G=p>>5, r5=p&31, gate=r5>>3, w=r5&7
__device__ __forceinline__ int grow_of(int p) {
    int G = p >> 5, r5 = p & 31;
    return (r5 >> 3) * 256 + G * 8 + (r5 & 7);
}

// ---------------------------------------------------------------------------
__global__ void k_prep_w(const float* __restrict__ wih, const float* __restrict__ whh,
                         const float* __restrict__ bih, const float* __restrict__ bhh) {
    int t = blockIdx.x * blockDim.x + threadIdx.x;
    if (t >= 1024 * KK) return;
    int p = t / KK, k = t % KK;
    int gr = grow_of(p);
    float v = (k < 128) ? wih[gr * 128 + k] : whh[gr * 256 + (k - 128)];
    bf16 hi = __float2bfloat16(v);
    g_whi[t] = hi;
    g_wlo[t] = __float2bfloat16(v - __bfloat162float(hi));
    if (k == 0) g_biasp[p] = bih[gr] + bhh[gr];
}

__global__ void k_prep_x(const float* __restrict__ x) {
    size_t t = (size_t)blockIdx.x * blockDim.x + threadIdx.x;
    if (t >= (size_t)NCELL * BB * 128) return;
    float v = x[t];
    bf16 hi = __float2bfloat16(v);
    g_xhi[t] = hi;
    g_xlo[t] = __float2bfloat16(v - __bfloat162float(hi));
}

__global__ void k_zero() {
    int t = blockIdx.x * blockDim.x + threadIdx.x;
    uint4 z = make_uint4(0, 0, 0, 0);
    if (t < 2 * 32 * BB * HH * 2 / 16) {
        reinterpret_cast<uint4*>(g_hrh)[t] = z;
        reinterpret_cast<uint4*>(g_hrl)[t] = z;
        reinterpret_cast<uint4*>(g_hch)[t] = z;
        reinterpret_cast<uint4*>(g_hcl)[t] = z;
        reinterpret_cast<uint4*>(g_crow)[2 * t] = z;
        reinterpret_cast<uint4*>(g_crow)[2 * t + 1] = z;
        reinterpret_cast<uint4*>(g_ccol)[2 * t] = z;
        reinterpret_cast<uint4*>(g_ccol)[2 * t + 1] = z;
    }
}

// ---------------------------------------------------------------------------
// One diagonal: grid=(16 unit-slices, nd cells), 256 threads (8 warps, 4m x 2n).
// Per CTA: gates[128m x 64p] = [x | h_row | h_col](128x384) @ Wperm^T, bf16
// split (hh, hl, lh). 3-stage cp.async pipeline, distance 2. 2 CTAs/SM.
// ---------------------------------------------------------------------------
#define PITCH 80
#define OFF_A_LO 10240            // A hi at 0, lo at +10240 (128 rows x 80B)
#define OFF_B_HI 20480            // B hi (64 rows x 80B)
#define OFF_B_LO 25600
#define STAGEB 30720
#define NSTAGE 3
#define SMEM_TOTAL (NSTAGE * STAGEB + 256)

__global__ __launch_bounds__(256, 2) void k_cell(int dd) {
    extern __shared__ char smem[];
    uint32_t sb = smem_u32(smem);
    int tid = threadIdx.x, lane = tid & 31, w = tid >> 5;
    int mw = w & 3, nw = w >> 2;

    int i = (dd < 32 ? 0 : dd - 31) + blockIdx.y;
    int j = dd - i;
    int U = blockIdx.x;           // 16 slices of 16 units (64 permuted cols)
    int par = dd & 1, qar = par ^ 1;
    int cell = i * 32 + j;

    const bf16* xh = g_xhi + (size_t)cell * BB * 128;
    const bf16* xl = g_xlo + (size_t)cell * BB * 128;
    const bf16* hrh = g_hrh + (par * 32 + i) * (BB * HH);
    const bf16* hrl = g_hrl + (par * 32 + i) * (BB * HH);
    const bf16* hch = g_hch + (par * 32 + j) * (BB * HH);
    const bf16* hcl = g_hcl + (par * 32 + j) * (BB * HH);

    // bias cache (64 cols per CTA)
    if (tid < 64)
        reinterpret_cast<float*>(smem + NSTAGE * STAGEB)[tid] = g_biasp[U * 64 + tid];

    // A loader: 128 rows x 32k x bf16 = 512 quads; thread -> row tid>>1, quads (tid&1)*2..+1
    int lr = tid >> 1, lq = (tid & 1) * 2;
    uint32_t soA = (uint32_t)lr * PITCH + lq * 16;
    // B loader: 64 rows x 32k = 256 quads; thread -> row tid>>2, quad tid&3
    int br = tid >> 2, bq = tid & 3;
    uint32_t soB = (uint32_t)br * PITCH + bq * 16;
    const bf16* bhp = g_whi + (size_t)(U * 64 + br) * KK + bq * 8;
    const bf16* blp = g_wlo + (size_t)(U * 64 + br) * KK + bq * 8;

    auto ld_chunk = [&](int kb, int s) {
        uint32_t st = sb + s * STAGEB;
        const bf16 *ah, *al;
        if (kb < 4)      { ah = xh  + lr * 128 + kb * 32;        al = xl  + lr * 128 + kb * 32; }
        else if (kb < 8) { ah = hrh + lr * 128 + (kb - 4) * 32;  al = hrl + lr * 128 + (kb - 4) * 32; }
        else             { ah = hch + lr * 128 + (kb - 8) * 32;  al = hcl + lr * 128 + (kb - 8) * 32; }
        CP16(st + soA,                 ah + lq * 8);
        CP16(st + soA + 16,            ah + lq * 8 + 8);
        CP16(st + OFF_A_LO + soA,      al + lq * 8);
        CP16(st + OFF_A_LO + soA + 16, al + lq * 8 + 8);
        CP16(st + OFF_B_HI + soB, bhp + kb * 32);
        CP16(st + OFF_B_LO + soB, blp + kb * 32);
    };

    float acc[2][4][4];
#pragma unroll
    for (int a = 0; a < 2; ++a)
#pragma unroll
        for (int b = 0; b < 4; ++b)
#pragma unroll
            for (int c = 0; c < 4; ++c) acc[a][b][c] = 0.f;

    // preload chunks 0,1 into stages 0,1
    ld_chunk(0, 0); CP_COMMIT();
    ld_chunk(1, 1); CP_COMMIT();

    // lane addressing for ldmatrix
    uint32_t a_off = (uint32_t)(lane & 15) * PITCH + ((lane >> 4) << 4);
    uint32_t b_row = (uint32_t)((lane & 7) + ((lane >> 4) << 3));
    uint32_t b_off = b_row * PITCH + (((lane >> 3) & 1) << 4);

    for (int kb = 0; kb < 12; ++kb) {
        int s = kb % 3;
        if (kb < 10) CP_WAIT1();    // chunk kb landed (kb+1 pending)
        else         CP_WAIT0();
        __syncthreads();            // data visible + stage (kb-1)%3 free
        if (kb < 10) { ld_chunk(kb + 2, (kb + 2) % 3); CP_COMMIT(); }
        uint32_t st = sb + s * STAGEB;
#pragma unroll
        for (int ks = 0; ks < 2; ++ks) {
            uint32_t ahi[2][4], alo[2][4];
#pragma unroll
            for (int mt = 0; mt < 2; ++mt) {
                uint32_t aa = st + (uint32_t)(mw * 32 + mt * 16) * PITCH + ks * 32 + a_off;
                LDSM4(ahi[mt], aa);
                LDSM4(alo[mt], aa + OFF_A_LO);
            }
            uint32_t bhi[2][4], blo[2][4];
#pragma unroll
            for (int bt = 0; bt < 2; ++bt) {
                uint32_t ba = st + OFF_B_HI + (uint32_t)(nw * 32 + bt * 16) * PITCH + ks * 32 + b_off;
                LDSM4(bhi[bt], ba);
                LDSM4(blo[bt], ba + (OFF_B_LO - OFF_B_HI));
            }
#pragma unroll
            for (int mt = 0; mt < 2; ++mt)
#pragma unroll
                for (int f = 0; f < 4; ++f) {
                    int bt = f >> 1, hf = (f & 1) * 2;
                    MMA(acc[mt][f], ahi[mt], bhi[bt][hf], bhi[bt][hf + 1]);
                    MMA(acc[mt][f], ahi[mt], blo[bt][hf], blo[bt][hf + 1]);
                    MMA(acc[mt][f], alo[mt], bhi[bt][hf], bhi[bt][hf + 1]);
                }
        }
    }

    // ---- epilogue: f == gate index; thread holds full (i,f,g,o) quadruples
    const float* bias_s = reinterpret_cast<const float*>(smem + NSTAGE * STAGEB);
    bool isrow = (U < 8);
    int ub = (U & 7) * 16;
    const float* csrc;
    float* cdst;
    bf16 *hdh, *hdl;
    if (isrow) {
        csrc = g_crow + (par * 32 + i) * (BB * HH);
        cdst = g_crow + (qar * 32 + i) * (BB * HH);
        hdh = g_hrh + (qar * 32 + i) * (BB * HH);
        hdl = g_hrl + (qar * 32 + i) * (BB * HH);
    } else {
        csrc = g_ccol + (par * 32 + j) * (BB * HH);
        cdst = g_ccol + (qar * 32 + j) * (BB * HH);
        hdh = g_hch + (qar * 32 + j) * (BB * HH);
        hdl = g_hcl + (qar * 32 + j) * (BB * HH);
    }

#pragma unroll
    for (int mt = 0; mt < 2; ++mt) {
        int m0 = mw * 32 + mt * 16 + (lane >> 2);
#pragma unroll
        for (int dr = 0; dr < 2; ++dr) {
            int m = m0 + dr * 8;
#pragma unroll
            for (int du = 0; du < 2; ++du) {
                int e = dr * 2 + du;
                int wslot = (lane & 3) * 2 + du;
                int pb = nw * 32 + wslot;          // bias col of gate 0
                float I = acc[mt][0][e] + bias_s[pb];
                float F = acc[mt][1][e] + bias_s[pb + 8];
                float G = acc[mt][2][e] + bias_s[pb + 16];
                float O = acc[mt][3][e] + bias_s[pb + 24];
                int idx = m * HH + ub + nw * 8 + wslot;
                float cold = csrc[idx];
                float cn = sigm_f(F) * cold + sigm_f(I) * tanh_f(G);
                float hn = sigm_f(O) * tanh_f(cn);
                cdst[idx] = cn;
                bf16 hh2 = __float2bfloat16(hn);
                hdh[idx] = hh2;
                hdl[idx] = __float2bfloat16(hn - __bfloat162float(hh2));
            }
        }
    }
}

// ---------------------------------------------------------------------------
__global__ void k_out(float* __restrict__ out, int out_size) {
    int t = blockIdx.x * blockDim.x + threadIdx.x;
    if (t >= out_size) return;
    int sel = t >> 15;        // 0=h, 1=c
    int r = t & 32767;
    int m = r >> 8;
    int u = r & 255;
    int base = (32 + 31) * (BB * HH);   // parity 1, line 31
    float v;
    if (u < HH) {
        int idx = base + m * HH + u;
        v = sel ? g_crow[idx]
                : (__bfloat162float(g_hrh[idx]) + __bfloat162float(g_hrl[idx]));
    } else {
        int idx = base + m * HH + (u - HH);
        v = sel ? g_ccol[idx]
                : (__bfloat162float(g_hch[idx]) + __bfloat162float(g_hcl[idx]));
    }
    out[t] = v;
}

// ---------------------------------------------------------------------------
extern "C" void kernel_launch(void* const* d_in, const int* in_sizes, int n_in,
                              void* d_out, int out_size) {
    const float* x   = (const float*)d_in[0];
    const float* wih = (const float*)d_in[1];
    const float* whh = (const float*)d_in[2];
    const float* bih = (const float*)d_in[3];
    const float* bhh = (const float*)d_in[4];

    cudaFuncSetAttribute(k_cell, cudaFuncAttributeMaxDynamicSharedMemorySize, SMEM_TOTAL);

    k_zero<<<1024, 256>>>();
    k_prep_w<<<(1024 * KK + 255) / 256, 256>>>(wih, whh, bih, bhh);
    k_prep_x<<<(int)(((size_t)NCELL * BB * 128 + 255) / 256), 256>>>(x);
    for (int d = 0; d < 63; ++d) {
        int nd = (d < 32) ? (d + 1) : (63 - d);
        k_cell<<<dim3(16, nd), 256, SMEM_TOTAL>>>(d);
    }
    k_out<<<(out_size + 255) / 256, 256>>>((float*)d_out, out_size);
}

// round 7
// speedup vs baseline: 5.4344x; 1.3293x over previous
#include <cuda_runtime.h>
#include <cuda_bf16.h>
#include <cstdint>
#include <math.h>

#define BB 128
#define HH 128

typedef __nv_bfloat16 bf16;

// ---------------- GMEM layouts (all pre-chunked + pre-swizzled) ----------------
// A-chunks: blocks of 16KB = [hi: 128 rows x 64B][lo: 128 rows x 64B]
//   row m, col c(0..31): elem = m*32 + ((c>>3 ^ ((m>>1)&3))<<3) + (c&7)
// B-chunks: blocks of 8KB = [hi: 64 rows x 64B][lo: ...] same swizzle
__device__ __align__(256) bf16  g_x[(size_t)1024 * 4 * 8192];   // [cell][chunk] 64MB
__device__ __align__(256) bf16  g_w[16 * 12 * 4096];            // [slice][chunk] 1.5MB
__device__ __align__(256) bf16  g_hr[2 * 32 * 4 * 8192];        // [par][line][chunk]
__device__ __align__(256) bf16  g_hc[2 * 32 * 4 * 8192];
__device__ __align__(256) float g_crow[2 * 32 * BB * HH];       // linear fp32
__device__ __align__(256) float g_ccol[2 * 32 * BB * HH];
__device__ float    g_biasp[1024];
__device__ unsigned g_done[1024];                               // per-cell slice counter

// ---------------- PTX helpers ----------------
__device__ __forceinline__ uint32_t smem_u32(const void* p) {
    uint32_t a;
    asm("{ .reg .u64 t; cvta.to.shared.u64 t, %1; cvt.u32.u64 %0, t; }" : "=r"(a) : "l"(p));
    return a;
}
#define MBAR_INIT(mbar, cnt) \
    asm volatile("mbarrier.init.shared.b64 [%0], %1;" :: "r"(mbar), "r"(cnt) : "memory")
#define MBAR_EXPECT(mbar, bytes) \
    asm volatile("mbarrier.arrive.expect_tx.shared.b64 _, [%0], %1;" :: "r"(mbar), "r"(bytes) : "memory")
__device__ __forceinline__ void tma_bulk(uint32_t dst, const void* src, uint32_t bytes, uint32_t mbar) {
    asm volatile("cp.async.bulk.shared::cta.global.mbarrier::complete_tx::bytes [%0], [%1], %2, [%3];"
                 :: "r"(dst), "l"(src), "r"(bytes), "r"(mbar) : "memory");
}
__device__ __forceinline__ void mbar_wait(uint32_t mbar, uint32_t parity) {
    uint32_t done;
    asm volatile(
        "{ .reg .pred p; mbarrier.try_wait.parity.acquire.cta.shared::cta.b64 p, [%1], %2;\n"
        "  selp.b32 %0, 1, 0, p; }"
        : "=r"(done) : "r"(mbar), "r"(parity) : "memory");
    if (!done) {
        asm volatile(
            "{ .reg .pred P1;\n"
            "WL_%=: mbarrier.try_wait.parity.acquire.cta.shared::cta.b64 P1, [%0], %1, 0x989680;\n"
            "@P1 bra.uni WD_%=;\n"
            "bra.uni WL_%=;\n"
            "WD_%=: }"
            :: "r"(mbar), "r"(parity) : "memory");
    }
}
#define LDSM4(r, addr) \
    asm volatile("ldmatrix.sync.aligned.m8n8.x4.shared.b16 {%0,%1,%2,%3}, [%4];" \
                 : "=r"((r)[0]), "=r"((r)[1]), "=r"((r)[2]), "=r"((r)[3]) : "r"(addr))
#define MMA(d, a, b0, b1) \
    asm volatile("mma.sync.aligned.m16n8k16.row.col.f32.bf16.bf16.f32 " \
                 "{%0,%1,%2,%3},{%4,%5,%6,%7},{%8,%9},{%0,%1,%2,%3};" \
                 : "+f"((d)[0]), "+f"((d)[1]), "+f"((d)[2]), "+f"((d)[3]) \
                 : "r"((a)[0]), "r"((a)[1]), "r"((a)[2]), "r"((a)[3]), "r"(b0), "r"(b1))

__device__ __forceinline__ float sigm_f(float x) { return __fdividef(1.0f, 1.0f + __expf(-x)); }
__device__ __forceinline__ float tanh_f(float x) { return fmaf(2.0f, sigm_f(2.0f * x), -1.0f); }

__device__ __forceinline__ void spinwait16(const unsigned* p) {
    unsigned v;
    while (true) {
        asm volatile("ld.acquire.gpu.global.u32 %0, [%1];" : "=r"(v) : "l"(p) : "memory");
        if (v >= 16) break;
        __nanosleep(64);
    }
}

// permuted col p -> original gate row (identical to verified Round-6 mapping)
__device__ __forceinline__ int grow_of(int p) {
    int G = p >> 5, r5 = p & 31;
    return (r5 >> 3) * 256 + G * 8 + (r5 & 7);
}
// swizzled element offset within a [rows x 32] chunk matrix
__device__ __forceinline__ int swz(int r, int c) {
    return r * 32 + ((((c >> 3) ^ ((r >> 1) & 3))) << 3) + (c & 7);
}

// ---------------- prep kernels ----------------
__global__ void k_prep_w(const float* __restrict__ wih, const float* __restrict__ whh,
                         const float* __restrict__ bih, const float* __restrict__ bhh) {
    int t = blockIdx.x * blockDim.x + threadIdx.x;   // 16*12*64*4 = 49152
    if (t >= 49152) return;
    int cu = t & 3, r = (t >> 2) & 63, t3 = t >> 8;
    int chunk = t3 % 12, U = t3 / 12;
    int p = U * 64 + r, gr = grow_of(p);
    const float* src = (chunk < 4) ? (wih + (size_t)gr * 128 + chunk * 32 + cu * 8)
                                   : (whh + (size_t)gr * 256 + (chunk - 4) * 32 + cu * 8);
    float f[8];
#pragma unroll
    for (int q = 0; q < 8; ++q) f[q] = src[q];
    unsigned short hi[8], lo[8];
#pragma unroll
    for (int q = 0; q < 8; ++q) {
        bf16 h = __float2bfloat16(f[q]);
        hi[q] = *reinterpret_cast<unsigned short*>(&h);
        bf16 l = __float2bfloat16(f[q] - __bfloat162float(h));
        lo[q] = *reinterpret_cast<unsigned short*>(&l);
    }
    bf16* dst = g_w + (size_t)(U * 12 + chunk) * 4096 + r * 32 + ((cu ^ ((r >> 1) & 3)) << 3);
    *reinterpret_cast<uint4*>(dst)        = *reinterpret_cast<uint4*>(hi);
    *reinterpret_cast<uint4*>(dst + 2048) = *reinterpret_cast<uint4*>(lo);
    if (chunk == 0 && cu == 0) g_biasp[p] = bih[gr] + bhh[gr];
}

__global__ void k_prep_x(const float* __restrict__ x) {
    int t = blockIdx.x * blockDim.x + threadIdx.x;   // 1024*128*4*4 = 2M
    if (t >= 1024 * 128 * 16) return;
    int cu = t & 3, chunk = (t >> 2) & 3, m = (t >> 4) & 127, cell = t >> 11;
    const float* src = x + ((size_t)cell * 128 + m) * 128 + chunk * 32 + cu * 8;
    float4 v0 = *reinterpret_cast<const float4*>(src);
    float4 v1 = *reinterpret_cast<const float4*>(src + 4);
    float f[8] = {v0.x, v0.y, v0.z, v0.w, v1.x, v1.y, v1.z, v1.w};
    unsigned short hi[8], lo[8];
#pragma unroll
    for (int q = 0; q < 8; ++q) {
        bf16 h = __float2bfloat16(f[q]);
        hi[q] = *reinterpret_cast<unsigned short*>(&h);
        bf16 l = __float2bfloat16(f[q] - __bfloat162float(h));
        lo[q] = *reinterpret_cast<unsigned short*>(&l);
    }
    bf16* dst = g_x + ((size_t)cell * 4 + chunk) * 8192 + m * 32 + ((cu ^ ((m >> 1) & 3)) << 3);
    *reinterpret_cast<uint4*>(dst)        = *reinterpret_cast<uint4*>(hi);
    *reinterpret_cast<uint4*>(dst + 4096) = *reinterpret_cast<uint4*>(lo);
}

__global__ void k_zero() {
    int t = blockIdx.x * blockDim.x + threadIdx.x;   // 262144 uint4 per array
    uint4 z = make_uint4(0, 0, 0, 0);
    if (t < 262144) {
        reinterpret_cast<uint4*>(g_hr)[t] = z;
        reinterpret_cast<uint4*>(g_hc)[t] = z;
        reinterpret_cast<uint4*>(g_crow)[t] = z;
        reinterpret_cast<uint4*>(g_ccol)[t] = z;
    }
    if (t < 1024) g_done[t] = 0;
}

// ---------------- persistent cell kernel ----------------
// Stage smem: [A hi 8K][A lo 8K][B hi 4K][B lo 4K] = 24KB, 3 stages, mbars after.
#define STAGEB 24576
#define MBAR_OFF 73728
#define SMEM_TOTAL (73728 + 64)

__global__ __launch_bounds__(256, 2) void k_persist(int P) {
    extern __shared__ char smem[];
    uint32_t sb = smem_u32(smem);
    const uint32_t MB = sb + MBAR_OFF;
    int tid = threadIdx.x, lane = tid & 31, w = tid >> 5;
    int mw = w & 3, nw = w >> 2;
    int ar = lane & 15, au = lane >> 4;
    int brl = (lane & 7) + ((lane >> 4) << 3);
    int bu = (lane >> 3) & 1;

    if (tid == 0) { MBAR_INIT(MB, 1); MBAR_INIT(MB + 8, 1); MBAR_INIT(MB + 16, 1); }
    __syncthreads();

    int b = blockIdx.x;
    for (int d = 0; d < 63; ++d) {
        int i0 = (d < 32) ? 0 : d - 31;
        int nd = (d < 32) ? d + 1 : 63 - d;
        int par = d & 1, qar = par ^ 1;
        for (int t = b; t < nd * 16; t += P) {
            int ci = i0 + (t >> 4);
            int j = d - ci;
            int U = t & 15;
            int cell = ci * 32 + j;

            if (tid == 0) {
                if (j > 0)  spinwait16(g_done + cell - 1);
                if (ci > 0) spinwait16(g_done + cell - 32);
            }
            __syncthreads();

            const bf16* ablk[3];   // rotating issue sources computed on the fly
            auto issue = [&](int kb, int s) {
                uint32_t st = sb + s * STAGEB;
                uint32_t mb = MB + s * 8;
                MBAR_EXPECT(mb, 24576);
                const bf16* asrc;
                if (kb < 4)      asrc = g_x + ((size_t)cell * 4 + kb) * 8192;
                else if (kb < 8) asrc = g_hr + ((size_t)(par * 32 + ci) * 4 + (kb - 4)) * 8192;
                else             asrc = g_hc + ((size_t)(par * 32 + j) * 4 + (kb - 8)) * 8192;
                tma_bulk(st, asrc, 16384, mb);
                tma_bulk(st + 16384, g_w + (size_t)(U * 12 + kb) * 4096, 8192, mb);
            };
            (void)ablk;

            if (tid == 0) { issue(0, 0); issue(1, 1); }

            float acc[2][4][4];
#pragma unroll
            for (int a = 0; a < 2; ++a)
#pragma unroll
                for (int f = 0; f < 4; ++f)
#pragma unroll
                    for (int e = 0; e < 4; ++e) acc[a][f][e] = 0.f;

            for (int kb = 0; kb < 12; ++kb) {
                int s = kb % 3;
                if (tid == 0 && kb < 10) issue(kb + 2, (kb + 2) % 3);
                mbar_wait(MB + s * 8, (kb / 3) & 1);
                uint32_t st = sb + s * STAGEB;
#pragma unroll
                for (int ks = 0; ks < 2; ++ks) {
                    uint32_t ahi[2][4], alo[2][4];
#pragma unroll
                    for (int mt = 0; mt < 2; ++mt) {
                        int row = mw * 32 + mt * 16 + ar;
                        uint32_t u = ks * 2 + au;
                        uint32_t aa = st + row * 64 + ((u ^ ((row >> 1) & 3)) << 4);
                        LDSM4(ahi[mt], aa);
                        LDSM4(alo[mt], aa + 8192);
                    }
                    uint32_t bhi[2][4], blo[2][4];
#pragma unroll
                    for (int bt = 0; bt < 2; ++bt) {
                        int brow = nw * 32 + bt * 16 + brl;
                        uint32_t u2 = ks * 2 + bu;
                        uint32_t ba = st + 16384 + brow * 64 + ((u2 ^ ((brow >> 1) & 3)) << 4);
                        LDSM4(bhi[bt], ba);
                        LDSM4(blo[bt], ba + 4096);
                    }
#pragma unroll
                    for (int mt = 0; mt < 2; ++mt)
#pragma unroll
                        for (int f = 0; f < 4; ++f) {
                            int bt = f >> 1, hf = (f & 1) * 2;
                            MMA(acc[mt][f], ahi[mt], bhi[bt][hf], bhi[bt][hf + 1]);
                            MMA(acc[mt][f], ahi[mt], blo[bt][hf], blo[bt][hf + 1]);
                            MMA(acc[mt][f], alo[mt], bhi[bt][hf], bhi[bt][hf + 1]);
                        }
                }
                __syncthreads();
            }

            // ---- epilogue (Round-6 verified mapping; new h addressing) ----
            bool isrow = (U < 8);
            int ub = (U & 7) * 16;
            int line = isrow ? ci : j;
            const float* csrc = (isrow ? g_crow : g_ccol) + (par * 32 + line) * (BB * HH);
            float* cdst       = (isrow ? g_crow : g_ccol) + (qar * 32 + line) * (BB * HH);
            bf16* hdst        = (isrow ? g_hr : g_hc);
            size_t hblk       = (size_t)(qar * 32 + line) * 4;

#pragma unroll
            for (int mt = 0; mt < 2; ++mt) {
                int m0 = mw * 32 + mt * 16 + (lane >> 2);
#pragma unroll
                for (int dr = 0; dr < 2; ++dr) {
                    int m = m0 + dr * 8;
#pragma unroll
                    for (int du = 0; du < 2; ++du) {
                        int e = dr * 2 + du;
                        int wslot = (lane & 3) * 2 + du;
                        int pb = nw * 32 + wslot;
                        float I = acc[mt][0][e] + g_biasp[U * 64 + pb];
                        float F = acc[mt][1][e] + g_biasp[U * 64 + pb + 8];
                        float G = acc[mt][2][e] + g_biasp[U * 64 + pb + 16];
                        float O = acc[mt][3][e] + g_biasp[U * 64 + pb + 24];
                        int ug = ub + nw * 8 + wslot;
                        int cidx = m * HH + ug;
                        float cold = __ldcg(csrc + cidx);
                        float cn = sigm_f(F) * cold + sigm_f(I) * tanh_f(G);
                        float hn = sigm_f(O) * tanh_f(cn);
                        cdst[cidx] = cn;
                        bf16 hh2 = __float2bfloat16(hn);
                        bf16 hl2 = __float2bfloat16(hn - __bfloat162float(hh2));
                        size_t he = (hblk + (ug >> 5)) * 8192 + swz(m, ug & 31);
                        hdst[he] = hh2;
                        hdst[he + 4096] = hl2;
                    }
                }
            }
            __threadfence();
            __syncthreads();
            if (tid == 0) atomicAdd(g_done + cell, 1u);
        }
    }
}

// ---------------- output pack ----------------
__global__ void k_out(float* __restrict__ out, int out_size) {
    int t = blockIdx.x * blockDim.x + threadIdx.x;
    if (t >= out_size) return;
    int sel = t >> 15;        // 0=h, 1=c
    int r = t & 32767;
    int m = r >> 8;
    int u = r & 255;
    float v;
    if (u < HH) {
        if (sel) v = g_crow[(32 + 31) * (BB * HH) + m * HH + u];
        else {
            size_t he = (size_t)((32 + 31) * 4 + (u >> 5)) * 8192 + swz(m, u & 31);
            v = __bfloat162float(g_hr[he]) + __bfloat162float(g_hr[he + 4096]);
        }
    } else {
        int uu = u - HH;
        if (sel) v = g_ccol[(32 + 31) * (BB * HH) + m * HH + uu];
        else {
            size_t he = (size_t)((32 + 31) * 4 + (uu >> 5)) * 8192 + swz(m, uu & 31);
            v = __bfloat162float(g_hc[he]) + __bfloat162float(g_hc[he + 4096]);
        }
    }
    out[t] = v;
}

// ---------------------------------------------------------------------------
extern "C" void kernel_launch(void* const* d_in, const int* in_sizes, int n_in,
                              void* d_out, int out_size) {
    const float* x   = (const float*)d_in[0];
    const float* wih = (const float*)d_in[1];
    const float* whh = (const float*)d_in[2];
    const float* bih = (const float*)d_in[3];
    const float* bhh = (const float*)d_in[4];

    cudaFuncSetAttribute(k_persist, cudaFuncAttributeMaxDynamicSharedMemorySize, SMEM_TOTAL);

    int dev = 0;
    cudaGetDevice(&dev);
    int nsm = 0;
    cudaDeviceGetAttribute(&nsm, cudaDevAttrMultiProcessorCount, dev);
    int occ = 0;
    cudaOccupancyMaxActiveBlocksPerMultiprocessor(&occ, k_persist, 256, SMEM_TOTAL);
    if (occ < 1) occ = 1;
    int P = nsm * occ;
    if (P > 512) P = 512;

    k_zero<<<1024, 256>>>();
    k_prep_w<<<192, 256>>>(wih, whh, bih, bhh);
    k_prep_x<<<8192, 256>>>(x);
    k_persist<<<P, 256, SMEM_TOTAL>>>(P);
    k_out<<<(out_size + 255) / 256, 256>>>((float*)d_out, out_size);
}

// round 9
// speedup vs baseline: 6.6631x; 1.2261x over previous
#include <cuda_runtime.h>
#include <cuda_fp16.h>
#include <cstdint>
#include <math.h>

#define BB 128
#define HH 128

typedef __half h16;

// ---------------- GMEM layouts (all pre-chunked + pre-swizzled) ----------------
// A-chunks: blocks of 8192 h16 = [hi: 128 rows x 32][lo: 128 rows x 32], swizzled
//   row m, col c(0..31): elem = m*32 + ((c>>3 ^ ((m>>1)&3))<<3) + (c&7)
// B-chunks: blocks of 2048 h16 = [64 rows x 32] single fp16, same swizzle
__device__ __align__(256) h16   g_x[(size_t)1024 * 4 * 8192];   // [cell][chunk] 64MB
__device__ __align__(256) h16   g_w[16 * 12 * 2048];            // [slice][chunk] 0.75MB
__device__ __align__(256) h16   g_hr[2 * 32 * 4 * 8192];        // [par][line][chunk]
__device__ __align__(256) h16   g_hc[2 * 32 * 4 * 8192];
__device__ __align__(256) float g_crow[2 * 32 * BB * HH];       // linear fp32
__device__ __align__(256) float g_ccol[2 * 32 * BB * HH];
__device__ float    g_biasp[1024];
__device__ unsigned g_done[1024];                               // per-cell slice counter

// ---------------- PTX helpers ----------------
__device__ __forceinline__ uint32_t smem_u32(const void* p) {
    uint32_t a;
    asm("{ .reg .u64 t; cvta.to.shared.u64 t, %1; cvt.u32.u64 %0, t; }" : "=r"(a) : "l"(p));
    return a;
}
#define MBAR_INIT(mbar, cnt) \
    asm volatile("mbarrier.init.shared.b64 [%0], %1;" :: "r"(mbar), "r"(cnt) : "memory")
#define MBAR_EXPECT(mbar, bytes) \
    asm volatile("mbarrier.arrive.expect_tx.shared.b64 _, [%0], %1;" :: "r"(mbar), "r"(bytes) : "memory")
__device__ __forceinline__ void tma_bulk(uint32_t dst, const void* src, uint32_t bytes, uint32_t mbar) {
    asm volatile("cp.async.bulk.shared::cta.global.mbarrier::complete_tx::bytes [%0], [%1], %2, [%3];"
                 :: "r"(dst), "l"(src), "r"(bytes), "r"(mbar) : "memory");
}
__device__ __forceinline__ void mbar_wait(uint32_t mbar, uint32_t parity) {
    uint32_t done;
    asm volatile(
        "{ .reg .pred p; mbarrier.try_wait.parity.acquire.cta.shared::cta.b64 p, [%1], %2;\n"
        "  selp.b32 %0, 1, 0, p; }"
        : "=r"(done) : "r"(mbar), "r"(parity) : "memory");
    if (!done) {
        asm volatile(
            "{ .reg .pred P1;\n"
            "WL_%=: mbarrier.try_wait.parity.acquire.cta.shared::cta.b64 P1, [%0], %1, 0x989680;\n"
            "@P1 bra.uni WD_%=;\n"
            "bra.uni WL_%=;\n"
            "WD_%=: }"
            :: "r"(mbar), "r"(parity) : "memory");
    }
}
#define LDSM4(r, addr) \
    asm volatile("ldmatrix.sync.aligned.m8n8.x4.shared.b16 {%0,%1,%2,%3}, [%4];" \
                 : "=r"((r)[0]), "=r"((r)[1]), "=r"((r)[2]), "=r"((r)[3]) : "r"(addr))
#define MMA(d, a, b0, b1) \
    asm volatile("mma.sync.aligned.m16n8k16.row.col.f32.f16.f16.f32 " \
                 "{%0,%1,%2,%3},{%4,%5,%6,%7},{%8,%9},{%0,%1,%2,%3};" \
                 : "+f"((d)[0]), "+f"((d)[1]), "+f"((d)[2]), "+f"((d)[3]) \
                 : "r"((a)[0]), "r"((a)[1]), "r"((a)[2]), "r"((a)[3]), "r"(b0), "r"(b1))

__device__ __forceinline__ float sigm_f(float x) { return __fdividef(1.0f, 1.0f + __expf(-x)); }
__device__ __forceinline__ float tanh_f(float x) { return fmaf(2.0f, sigm_f(2.0f * x), -1.0f); }

__device__ __forceinline__ void spinwait16(const unsigned* p) {
    unsigned v;
    while (true) {
        asm volatile("ld.acquire.gpu.global.u32 %0, [%1];" : "=r"(v) : "l"(p) : "memory");
        if (v >= 16) break;
        __nanosleep(64);
    }
}

// permuted col p -> original gate row (verified mapping)
__device__ __forceinline__ int grow_of(int p) {
    int G = p >> 5, r5 = p & 31;
    return (r5 >> 3) * 256 + G * 8 + (r5 & 7);
}
// swizzled element offset within a [rows x 32] chunk matrix
__device__ __forceinline__ int swz(int r, int c) {
    return r * 32 + ((((c >> 3) ^ ((r >> 1) & 3))) << 3) + (c & 7);
}

// ---------------- prep kernels ----------------
__global__ void k_prep_w(const float* __restrict__ wih, const float* __restrict__ whh,
                         const float* __restrict__ bih, const float* __restrict__ bhh) {
    int t = blockIdx.x * blockDim.x + threadIdx.x;   // 16*12*64*4 = 49152
    if (t >= 49152) return;
    int cu = t & 3, r = (t >> 2) & 63, t3 = t >> 8;
    int chunk = t3 % 12, U = t3 / 12;
    int p = U * 64 + r, gr = grow_of(p);
    const float* src = (chunk < 4) ? (wih + (size_t)gr * 128 + chunk * 32 + cu * 8)
                                   : (whh + (size_t)gr * 256 + (chunk - 4) * 32 + cu * 8);
    unsigned short hv[8];
#pragma unroll
    for (int q = 0; q < 8; ++q) {
        h16 h = __float2half_rn(src[q]);
        hv[q] = *reinterpret_cast<unsigned short*>(&h);
    }
    h16* dst = g_w + (size_t)(U * 12 + chunk) * 2048 + r * 32 + ((cu ^ ((r >> 1) & 3)) << 3);
    *reinterpret_cast<uint4*>(dst) = *reinterpret_cast<uint4*>(hv);
    if (chunk == 0 && cu == 0) g_biasp[p] = bih[gr] + bhh[gr];
}

__global__ void k_prep_x(const float* __restrict__ x) {
    int t = blockIdx.x * blockDim.x + threadIdx.x;   // 1024*128*4*4 = 2M
    if (t >= 1024 * 128 * 16) return;
    int cu = t & 3, chunk = (t >> 2) & 3, m = (t >> 4) & 127, cell = t >> 11;
    const float* src = x + ((size_t)cell * 128 + m) * 128 + chunk * 32 + cu * 8;
    float4 v0 = *reinterpret_cast<const float4*>(src);
    float4 v1 = *reinterpret_cast<const float4*>(src + 4);
    float f[8] = {v0.x, v0.y, v0.z, v0.w, v1.x, v1.y, v1.z, v1.w};
    unsigned short hi[8], lo[8];
#pragma unroll
    for (int q = 0; q < 8; ++q) {
        h16 h = __float2half_rn(f[q]);
        hi[q] = *reinterpret_cast<unsigned short*>(&h);
        h16 l = __float2half_rn(f[q] - __half2float(h));
        lo[q] = *reinterpret_cast<unsigned short*>(&l);
    }
    h16* dst = g_x + ((size_t)cell * 4 + chunk) * 8192 + m * 32 + ((cu ^ ((m >> 1) & 3)) << 3);
    *reinterpret_cast<uint4*>(dst)        = *reinterpret_cast<uint4*>(hi);
    *reinterpret_cast<uint4*>(dst + 4096) = *reinterpret_cast<uint4*>(lo);
}

__global__ void k_zero() {
    int t = blockIdx.x * blockDim.x + threadIdx.x;   // 262144 uint4 per array
    uint4 z = make_uint4(0, 0, 0, 0);
    if (t < 262144) {
        reinterpret_cast<uint4*>(g_hr)[t] = z;
        reinterpret_cast<uint4*>(g_hc)[t] = z;
        reinterpret_cast<uint4*>(g_crow)[t] = z;
        reinterpret_cast<uint4*>(g_ccol)[t] = z;
    }
    if (t < 1024) g_done[t] = 0;
}

// ---------------- persistent cell kernel ----------------
// Stage smem: [A hi 8K][A lo 8K][B 4K] = 20KB, 3 stages, mbars after.
#define STAGEB 20480
#define MBAR_OFF 61440
#define SMEM_TOTAL (61440 + 64)

__global__ __launch_bounds__(256, 2) void k_persist(int P) {
    extern __shared__ char smem[];
    uint32_t sb = smem_u32(smem);
    const uint32_t MB = sb + MBAR_OFF;
    int tid = threadIdx.x, lane = tid & 31, w = tid >> 5;
    int mw = w & 3, nw = w >> 2;
    int ar = lane & 15, au = lane >> 4;
    int brl = (lane & 7) + ((lane >> 4) << 3);
    int bu = (lane >> 3) & 1;

    if (tid == 0) { MBAR_INIT(MB, 1); MBAR_INIT(MB + 8, 1); MBAR_INIT(MB + 16, 1); }
    __syncthreads();

    int b = blockIdx.x;
    for (int d = 0; d < 63; ++d) {
        int i0 = (d < 32) ? 0 : d - 31;
        int nd = (d < 32) ? d + 1 : 63 - d;
        int par = d & 1, qar = par ^ 1;
        for (int t = b; t < nd * 16; t += P) {
            int ci = i0 + (t >> 4);
            int j = d - ci;
            int U = t & 15;
            int cell = ci * 32 + j;

            if (tid == 0) {
                if (j > 0)  spinwait16(g_done + cell - 1);
                if (ci > 0) spinwait16(g_done + cell - 32);
            }
            __syncthreads();

            auto issue = [&](int kb, int s) {
                uint32_t st = sb + s * STAGEB;
                uint32_t mb = MB + s * 8;
                MBAR_EXPECT(mb, 20480);
                const h16* asrc;
                if (kb < 4)      asrc = g_x + ((size_t)cell * 4 + kb) * 8192;
                else if (kb < 8) asrc = g_hr + ((size_t)(par * 32 + ci) * 4 + (kb - 4)) * 8192;
                else             asrc = g_hc + ((size_t)(par * 32 + j) * 4 + (kb - 8)) * 8192;
                tma_bulk(st, asrc, 16384, mb);
                tma_bulk(st + 16384, g_w + (size_t)(U * 12 + kb) * 2048, 4096, mb);
            };

            if (tid == 0) { issue(0, 0); issue(1, 1); }

            float acc[2][4][4];
#pragma unroll
            for (int a = 0; a < 2; ++a)
#pragma unroll
                for (int f = 0; f < 4; ++f)
#pragma unroll
                    for (int e = 0; e < 4; ++e) acc[a][f][e] = 0.f;

            for (int kb = 0; kb < 12; ++kb) {
                int s = kb % 3;
                if (tid == 0 && kb < 10) issue(kb + 2, (kb + 2) % 3);
                mbar_wait(MB + s * 8, (kb / 3) & 1);
                uint32_t st = sb + s * STAGEB;
#pragma unroll
                for (int ks = 0; ks < 2; ++ks) {
                    uint32_t ahi[2][4], alo[2][4];
#pragma unroll
                    for (int mt = 0; mt < 2; ++mt) {
                        int row = mw * 32 + mt * 16 + ar;
                        uint32_t u = ks * 2 + au;
                        uint32_t aa = st + row * 64 + ((u ^ ((row >> 1) & 3)) << 4);
                        LDSM4(ahi[mt], aa);
                        LDSM4(alo[mt], aa + 8192);
                    }
                    uint32_t bfr[2][4];
#pragma unroll
                    for (int bt = 0; bt < 2; ++bt) {
                        int brow = nw * 32 + bt * 16 + brl;
                        uint32_t u2 = ks * 2 + bu;
                        uint32_t ba = st + 16384 + brow * 64 + ((u2 ^ ((brow >> 1) & 3)) << 4);
                        LDSM4(bfr[bt], ba);
                    }
#pragma unroll
                    for (int mt = 0; mt < 2; ++mt)
#pragma unroll
                        for (int f = 0; f < 4; ++f) {
                            int bt = f >> 1, hf = (f & 1) * 2;
                            MMA(acc[mt][f], ahi[mt], bfr[bt][hf], bfr[bt][hf + 1]);
                            MMA(acc[mt][f], alo[mt], bfr[bt][hf], bfr[bt][hf + 1]);
                        }
                }
                __syncthreads();
            }

            // ---- epilogue (verified mapping) ----
            bool isrow = (U < 8);
            int ub = (U & 7) * 16;
            int line = isrow ? ci : j;
            const float* csrc = (isrow ? g_crow : g_ccol) + (par * 32 + line) * (BB * HH);
            float* cdst       = (isrow ? g_crow : g_ccol) + (qar * 32 + line) * (BB * HH);
            h16* hdst         = (isrow ? g_hr : g_hc);
            size_t hblk       = (size_t)(qar * 32 + line) * 4;

#pragma unroll
            for (int mt = 0; mt < 2; ++mt) {
                int m0 = mw * 32 + mt * 16 + (lane >> 2);
#pragma unroll
                for (int dr = 0; dr < 2; ++dr) {
                    int m = m0 + dr * 8;
#pragma unroll
                    for (int du = 0; du < 2; ++du) {
                        int e = dr * 2 + du;
                        int wslot = (lane & 3) * 2 + du;
                        int pb = nw * 32 + wslot;
                        float I = acc[mt][0][e] + g_biasp[U * 64 + pb];
                        float F = acc[mt][1][e] + g_biasp[U * 64 + pb + 8];
                        float G = acc[mt][2][e] + g_biasp[U * 64 + pb + 16];
                        float O = acc[mt][3][e] + g_biasp[U * 64 + pb + 24];
                        int ug = ub + nw * 8 + wslot;
                        int cidx = m * HH + ug;
                        float cold = __ldcg(csrc + cidx);
                        float cn = sigm_f(F) * cold + sigm_f(I) * tanh_f(G);
                        float hn = sigm_f(O) * tanh_f(cn);
                        cdst[cidx] = cn;
                        h16 hh2 = __float2half_rn(hn);
                        h16 hl2 = __float2half_rn(hn - __half2float(hh2));
                        size_t he = (hblk + (ug >> 5)) * 8192 + swz(m, ug & 31);
                        hdst[he] = hh2;
                        hdst[he + 4096] = hl2;
                    }
                }
            }
            __threadfence();
            __syncthreads();
            if (tid == 0) atomicAdd(g_done + cell, 1u);
        }
    }
}

// ---------------- output pack ----------------
__global__ void k_out(float* __restrict__ out, int out_size) {
    int t = blockIdx.x * blockDim.x + threadIdx.x;
    if (t >= out_size) return;
    int sel = t >> 15;        // 0=h, 1=c
    int r = t & 32767;
    int m = r >> 8;
    int u = r & 255;
    float v;
    if (u < HH) {
        if (sel) v = g_crow[(32 + 31) * (BB * HH) + m * HH + u];
        else {
            size_t he = (size_t)((32 + 31) * 4 + (u >> 5)) * 8192 + swz(m, u & 31);
            v = __half2float(g_hr[he]) + __half2float(g_hr[he + 4096]);
        }
    } else {
        int uu = u - HH;
        if (sel) v = g_ccol[(32 + 31) * (BB * HH) + m * HH + uu];
        else {
            size_t he = (size_t)((32 + 31) * 4 + (uu >> 5)) * 8192 + swz(m, uu & 31);
            v = __half2float(g_hc[he]) + __half2float(g_hc[he + 4096]);
        }
    }
    out[t] = v;
}

// ---------------------------------------------------------------------------
extern "C" void kernel_launch(void* const* d_in, const int* in_sizes, int n_in,
                              void* d_out, int out_size) {
    const float* x   = (const float*)d_in[0];
    const float* wih = (const float*)d_in[1];
    const float* whh = (const float*)d_in[2];
    const float* bih = (const float*)d_in[3];
    const float* bhh = (const float*)d_in[4];

    cudaFuncSetAttribute(k_persist, cudaFuncAttributeMaxDynamicSharedMemorySize, SMEM_TOTAL);

    int dev = 0;
    cudaGetDevice(&dev);
    int nsm = 0;
    cudaDeviceGetAttribute(&nsm, cudaDevAttrMultiProcessorCount, dev);
    int occ = 0;
    cudaOccupancyMaxActiveBlocksPerMultiprocessor(&occ, k_persist, 256, SMEM_TOTAL);
    if (occ < 1) occ = 1;
    int P = nsm * occ;
    if (P > 512) P = 512;

    k_zero<<<1024, 256>>>();
    k_prep_w<<<192, 256>>>(wih, whh, bih, bhh);
    k_prep_x<<<8192, 256>>>(x);
    k_persist<<<P, 256, SMEM_TOTAL>>>(P);
    k_out<<<(out_size + 255) / 256, 256>>>((float*)d_out, out_size);
}

// round 10
// speedup vs baseline: 7.8003x; 1.1707x over previous
#include <cuda_runtime.h>
#include <cuda_fp16.h>
#include <cstdint>
#include <math.h>

#define BB 128
#define HH 128

typedef __half h16;

// ---------------- GMEM layouts ----------------
// A-chunk (K=64): 16384 h16 = [hi: 128r x 64c][lo: 128r x 64c], 128B-row swizzle
//   swz64(r,c) = r*64 + (((c>>3) ^ (r&7))<<3) + (c&7)
// B-chunk: 4096 h16 = [64r x 64c], same swizzle
__device__ __align__(256) h16   g_x[(size_t)1024 * 32768];      // [cell][2 chunks] 64MB
__device__ __align__(256) h16   g_w[16 * 6 * 4096];             // [slice][6 chunks]
__device__ __align__(256) h16   g_hr[(size_t)64 * 32768];       // [par*32+line][2 chunks]
__device__ __align__(256) h16   g_hc[(size_t)64 * 32768];
__device__ __align__(256) float g_crow[2 * 32 * BB * HH];
__device__ __align__(256) float g_ccol[2 * 32 * BB * HH];
__device__ float    g_biasp[1024];
__device__ unsigned g_done[1024];

// ---------------- PTX helpers ----------------
__device__ __forceinline__ uint32_t smem_u32(const void* p) {
    uint32_t a;
    asm("{ .reg .u64 t; cvta.to.shared.u64 t, %1; cvt.u32.u64 %0, t; }" : "=r"(a) : "l"(p));
    return a;
}
#define MBAR_INIT(mbar, cnt) \
    asm volatile("mbarrier.init.shared.b64 [%0], %1;" :: "r"(mbar), "r"(cnt) : "memory")
#define MBAR_EXPECT(mbar, bytes) \
    asm volatile("mbarrier.arrive.expect_tx.shared.b64 _, [%0], %1;" :: "r"(mbar), "r"(bytes) : "memory")
__device__ __forceinline__ void tma_bulk(uint32_t dst, const void* src, uint32_t bytes, uint32_t mbar) {
    asm volatile("cp.async.bulk.shared::cta.global.mbarrier::complete_tx::bytes [%0], [%1], %2, [%3];"
                 :: "r"(dst), "l"(src), "r"(bytes), "r"(mbar) : "memory");
}
__device__ __forceinline__ void mbar_wait(uint32_t mbar, uint32_t parity) {
    uint32_t done;
    asm volatile(
        "{ .reg .pred p; mbarrier.try_wait.parity.acquire.cta.shared::cta.b64 p, [%1], %2;\n"
        "  selp.b32 %0, 1, 0, p; }"
        : "=r"(done) : "r"(mbar), "r"(parity) : "memory");
    if (!done) {
        asm volatile(
            "{ .reg .pred P1;\n"
            "WL_%=: mbarrier.try_wait.parity.acquire.cta.shared::cta.b64 P1, [%0], %1, 0x989680;\n"
            "@P1 bra.uni WD_%=;\n"
            "bra.uni WL_%=;\n"
            "WD_%=: }"
            :: "r"(mbar), "r"(parity) : "memory");
    }
}
#define LDSM4(r, addr) \
    asm volatile("ldmatrix.sync.aligned.m8n8.x4.shared.b16 {%0,%1,%2,%3}, [%4];" \
                 : "=r"((r)[0]), "=r"((r)[1]), "=r"((r)[2]), "=r"((r)[3]) : "r"(addr))
#define MMA(d, a, b0, b1) \
    asm volatile("mma.sync.aligned.m16n8k16.row.col.f32.f16.f16.f32 " \
                 "{%0,%1,%2,%3},{%4,%5,%6,%7},{%8,%9},{%0,%1,%2,%3};" \
                 : "+f"((d)[0]), "+f"((d)[1]), "+f"((d)[2]), "+f"((d)[3]) \
                 : "r"((a)[0]), "r"((a)[1]), "r"((a)[2]), "r"((a)[3]), "r"(b0), "r"(b1))

__device__ __forceinline__ float sigm_f(float x) { return __fdividef(1.0f, 1.0f + __expf(-x)); }
__device__ __forceinline__ float tanh_f(float x) { return fmaf(2.0f, sigm_f(2.0f * x), -1.0f); }

__device__ __forceinline__ void spinwait16(const unsigned* p) {
    unsigned v;
    do {
        asm volatile("ld.acquire.gpu.global.u32 %0, [%1];" : "=r"(v) : "l"(p) : "memory");
    } while (v < 16);
}

// permuted col p -> original gate row (verified mapping)
__device__ __forceinline__ int grow_of(int p) {
    int G = p >> 5, r5 = p & 31;
    return (r5 >> 3) * 256 + G * 8 + (r5 & 7);
}
// swizzled elem offset in a [rows x 64] chunk (128B rows)
__device__ __forceinline__ int swz64(int r, int c) {
    return r * 64 + ((((c >> 3) ^ (r & 7))) << 3) + (c & 7);
}

// ---------------- prep kernels ----------------
__global__ void k_prep_w(const float* __restrict__ wih, const float* __restrict__ whh,
                         const float* __restrict__ bih, const float* __restrict__ bhh) {
    int t = blockIdx.x * blockDim.x + threadIdx.x;   // 16*6*64*8 = 49152
    if (t >= 49152) return;
    int u = t & 7, r = (t >> 3) & 63, t3 = t >> 9;
    int chunk = t3 % 6, U = t3 / 6;
    int p = U * 64 + r, gr = grow_of(p);
    const float* src = (chunk < 2) ? (wih + (size_t)gr * 128 + chunk * 64 + u * 8)
                                   : (whh + (size_t)gr * 256 + (chunk - 2) * 64 + u * 8);
    unsigned short hv[8];
#pragma unroll
    for (int q = 0; q < 8; ++q) {
        h16 h = __float2half_rn(src[q]);
        hv[q] = *reinterpret_cast<unsigned short*>(&h);
    }
    h16* dst = g_w + (size_t)(U * 6 + chunk) * 4096 + r * 64 + ((u ^ (r & 7)) << 3);
    *reinterpret_cast<uint4*>(dst) = *reinterpret_cast<uint4*>(hv);
    if (chunk == 0 && u == 0) g_biasp[p] = bih[gr] + bhh[gr];
}

__global__ void k_prep_x(const float* __restrict__ x) {
    int t = blockIdx.x * blockDim.x + threadIdx.x;   // 1024*2*128*8 = 2M
    if (t >= 1024 * 2048) return;
    int u = t & 7, m = (t >> 3) & 127, chunk = (t >> 10) & 1, cell = t >> 11;
    const float* src = x + (size_t)cell * 16384 + m * 128 + chunk * 64 + u * 8;
    unsigned short hi[8], lo[8];
#pragma unroll
    for (int q = 0; q < 8; ++q) {
        float f = src[q];
        h16 h = __float2half_rn(f);
        hi[q] = *reinterpret_cast<unsigned short*>(&h);
        h16 l = __float2half_rn(f - __half2float(h));
        lo[q] = *reinterpret_cast<unsigned short*>(&l);
    }
    h16* dst = g_x + (size_t)cell * 32768 + chunk * 16384 + m * 64 + ((u ^ (m & 7)) << 3);
    *reinterpret_cast<uint4*>(dst)        = *reinterpret_cast<uint4*>(hi);
    *reinterpret_cast<uint4*>(dst + 8192) = *reinterpret_cast<uint4*>(lo);
}

__global__ void k_zero() {
    int t = blockIdx.x * blockDim.x + threadIdx.x;
    uint4 z = make_uint4(0, 0, 0, 0);
    if (t < 262144) {
        reinterpret_cast<uint4*>(g_hr)[t] = z;
        reinterpret_cast<uint4*>(g_hc)[t] = z;
        reinterpret_cast<uint4*>(g_crow)[t] = z;
        reinterpret_cast<uint4*>(g_ccol)[t] = z;
    }
    if (t < 1024) g_done[t] = 0;
}

// ---------------- persistent cell kernel ----------------
// Stage: [A hi 16K][A lo 16K][B 8K] = 40KB, 2 stages; mbars after.
#define STAGEB 40960
#define MBAR_OFF 81920
#define SMEM_TOTAL (81920 + 64)

__global__ __launch_bounds__(256, 2) void k_persist(int P) {
    extern __shared__ char smem[];
    uint32_t sb = smem_u32(smem);
    const uint32_t MB = sb + MBAR_OFF;
    int tid = threadIdx.x, lane = tid & 31, w = tid >> 5;
    int mw = w & 3, nw = w >> 2;
    int ar = lane & 15, au = lane >> 4;
    int brl = (lane & 7) + ((lane >> 4) << 3);
    int bu = (lane >> 3) & 1;

    if (tid == 0) { MBAR_INIT(MB, 1); MBAR_INIT(MB + 8, 1); }
    __syncthreads();

    int ph0 = 0, ph1 = 0;
    float acc[2][4][4];

    auto issueA = [&](const h16* a, const h16* wsrc, int s) {
        uint32_t st = sb + s * STAGEB;
        uint32_t mb = MB + s * 8;
        MBAR_EXPECT(mb, 40960);
        tma_bulk(st, a, 32768, mb);
        tma_bulk(st + 32768, wsrc, 8192, mb);
    };
    auto compute = [&](int s) {
        uint32_t st = sb + s * STAGEB;
#pragma unroll
        for (int ks = 0; ks < 4; ++ks) {
            uint32_t ahi[2][4], alo[2][4];
#pragma unroll
            for (int mt = 0; mt < 2; ++mt) {
                int row = mw * 32 + mt * 16 + ar;
                uint32_t u = ks * 2 + au;
                uint32_t aa = st + row * 128 + ((u ^ (row & 7)) << 4);
                LDSM4(ahi[mt], aa);
                LDSM4(alo[mt], aa + 16384);
            }
            uint32_t bfr[2][4];
#pragma unroll
            for (int bt = 0; bt < 2; ++bt) {
                int brow = nw * 32 + bt * 16 + brl;
                uint32_t u2 = ks * 2 + bu;
                uint32_t ba = st + 32768 + brow * 128 + ((u2 ^ (brow & 7)) << 4);
                LDSM4(bfr[bt], ba);
            }
#pragma unroll
            for (int mt = 0; mt < 2; ++mt)
#pragma unroll
                for (int f = 0; f < 4; ++f) {
                    int bt = f >> 1, hf = (f & 1) * 2;
                    MMA(acc[mt][f], ahi[mt], bfr[bt][hf], bfr[bt][hf + 1]);
                    MMA(acc[mt][f], alo[mt], bfr[bt][hf], bfr[bt][hf + 1]);
                }
        }
    };

    int b = blockIdx.x;
    for (int d = 0; d < 63; ++d) {
        int i0 = (d < 32) ? 0 : d - 31;
        int nd = (d < 32) ? d + 1 : 63 - d;
        int par = d & 1, qar = par ^ 1;
        for (int t = b; t < nd * 16; t += P) {
            int ci = i0 + (t >> 4);
            int j = d - ci;
            int U = t & 15;
            int cell = ci * 32 + j;
            const h16* wb = g_w + (size_t)U * 6 * 4096;

            // --- pre-dependency: x chunks (no dep on neighbors) ---
            if (tid == 0) {
                issueA(g_x + (size_t)cell * 32768,         wb,            0);
                issueA(g_x + (size_t)cell * 32768 + 16384, wb + 4096,     1);
            }
#pragma unroll
            for (int a = 0; a < 2; ++a)
#pragma unroll
                for (int f = 0; f < 4; ++f)
#pragma unroll
                    for (int e = 0; e < 4; ++e) acc[a][f][e] = 0.f;

            mbar_wait(MB, ph0); ph0 ^= 1; compute(0); __syncthreads();
            mbar_wait(MB + 8, ph1); ph1 ^= 1; compute(1); __syncthreads();

            // --- dependency gate, then h chunks ---
            if (tid == 0) {
                if (j > 0)  spinwait16(g_done + cell - 1);
                if (ci > 0) spinwait16(g_done + cell - 32);
                const h16* hr = g_hr + (size_t)(par * 32 + ci) * 32768;
                issueA(hr,          wb + 2 * 4096, 0);
                issueA(hr + 16384,  wb + 3 * 4096, 1);
            }
            mbar_wait(MB, ph0); ph0 ^= 1; compute(0); __syncthreads();
            if (tid == 0)
                issueA(g_hc + (size_t)(par * 32 + j) * 32768, wb + 4 * 4096, 0);
            mbar_wait(MB + 8, ph1); ph1 ^= 1; compute(1); __syncthreads();
            if (tid == 0)
                issueA(g_hc + (size_t)(par * 32 + j) * 32768 + 16384, wb + 5 * 4096, 1);
            mbar_wait(MB, ph0); ph0 ^= 1; compute(0); __syncthreads();
            mbar_wait(MB + 8, ph1); ph1 ^= 1; compute(1);

            // ---- epilogue (verified mapping) ----
            bool isrow = (U < 8);
            int ub = (U & 7) * 16;
            int line = isrow ? ci : j;
            const float* csrc = (isrow ? g_crow : g_ccol) + (par * 32 + line) * (BB * HH);
            float* cdst       = (isrow ? g_crow : g_ccol) + (qar * 32 + line) * (BB * HH);
            h16* hdst         = (isrow ? g_hr : g_hc);
            size_t hb         = (size_t)(qar * 32 + line) * 32768;

#pragma unroll
            for (int mt = 0; mt < 2; ++mt) {
                int m0 = mw * 32 + mt * 16 + (lane >> 2);
#pragma unroll
                for (int dr = 0; dr < 2; ++dr) {
                    int m = m0 + dr * 8;
#pragma unroll
                    for (int du = 0; du < 2; ++du) {
                        int e = dr * 2 + du;
                        int wslot = (lane & 3) * 2 + du;
                        int pb = nw * 32 + wslot;
                        float I = acc[mt][0][e] + g_biasp[U * 64 + pb];
                        float F = acc[mt][1][e] + g_biasp[U * 64 + pb + 8];
                        float G = acc[mt][2][e] + g_biasp[U * 64 + pb + 16];
                        float O = acc[mt][3][e] + g_biasp[U * 64 + pb + 24];
                        int ug = ub + nw * 8 + wslot;
                        int cidx = m * HH + ug;
                        float cold = __ldcg(csrc + cidx);
                        float cn = sigm_f(F) * cold + sigm_f(I) * tanh_f(G);
                        float hn = sigm_f(O) * tanh_f(cn);
                        cdst[cidx] = cn;
                        h16 hh2 = __float2half_rn(hn);
                        h16 hl2 = __float2half_rn(hn - __half2float(hh2));
                        size_t he = hb + (ug >> 6) * 16384 + swz64(m, ug & 63);
                        hdst[he] = hh2;
                        hdst[he + 8192] = hl2;
                    }
                }
            }
            __syncthreads();   // CTA writes done; bar.sync edge makes them visible to release
            if (tid == 0)
                asm volatile("red.release.gpu.global.add.u32 [%0], %1;"
                             :: "l"(g_done + cell), "r"(1u) : "memory");
        }
    }
}

// ---------------- output pack ----------------
__global__ void k_out(float* __restrict__ out, int out_size) {
    int t = blockIdx.x * blockDim.x + threadIdx.x;
    if (t >= out_size) return;
    int sel = t >> 15;        // 0=h, 1=c
    int r = t & 32767;
    int m = r >> 8;
    int u = r & 255;
    float v;
    if (u < HH) {
        if (sel) v = g_crow[(32 + 31) * (BB * HH) + m * HH + u];
        else {
            size_t he = (size_t)63 * 32768 + (u >> 6) * 16384 + swz64(m, u & 63);
            v = __half2float(g_hr[he]) + __half2float(g_hr[he + 8192]);
        }
    } else {
        int uu = u - HH;
        if (sel) v = g_ccol[(32 + 31) * (BB * HH) + m * HH + uu];
        else {
            size_t he = (size_t)63 * 32768 + (uu >> 6) * 16384 + swz64(m, uu & 63);
            v = __half2float(g_hc[he]) + __half2float(g_hc[he + 8192]);
        }
    }
    out[t] = v;
}

// ---------------------------------------------------------------------------
extern "C" void kernel_launch(void* const* d_in, const int* in_sizes, int n_in,
                              void* d_out, int out_size) {
    const float* x   = (const float*)d_in[0];
    const float* wih = (const float*)d_in[1];
    const float* whh = (const float*)d_in[2];
    const float* bih = (const float*)d_in[3];
    const float* bhh = (const float*)d_in[4];

    cudaFuncSetAttribute(k_persist, cudaFuncAttributeMaxDynamicSharedMemorySize, SMEM_TOTAL);

    int dev = 0;
    cudaGetDevice(&dev);
    int nsm = 0;
    cudaDeviceGetAttribute(&nsm, cudaDevAttrMultiProcessorCount, dev);
    int occ = 0;
    cudaOccupancyMaxActiveBlocksPerMultiprocessor(&occ, k_persist, 256, SMEM_TOTAL);
    if (occ < 1) occ = 1;
    int P = nsm * occ;
    if (P > 512) P = 512;

    k_zero<<<1024, 256>>>();
    k_prep_w<<<192, 256>>>(wih, whh, bih, bhh);
    k_prep_x<<<8192, 256>>>(x);
    k_persist<<<P, 256, SMEM_TOTAL>>>(P);
    k_out<<<(out_size + 255) / 256, 256>>>((float*)d_out, out_size);
}

// round 11
// speedup vs baseline: 10.1363x; 1.2995x over previous
#include <cuda_runtime.h>
#include <cuda_fp16.h>
#include <cstdint>
#include <math.h>

#define BB 128
#define HH 128

typedef __half h16;

// ---------------- GMEM layouts ----------------
// A-chunk (K=64): 8192 h16 = [128r x 64c] fp16, 128B-row swizzle
//   swz64(r,c) = r*64 + (((c>>3) ^ (r&7))<<3) + (c&7)
// B-chunk: 4096 h16 = [64r x 64c], same swizzle
__device__ __align__(256) h16   g_x[(size_t)1024 * 16384];      // [cell][2 chunks] 32MB
__device__ __align__(256) h16   g_w[16 * 6 * 4096];             // [slice][6 chunks]
__device__ __align__(256) h16   g_hr[(size_t)64 * 16384];       // [par*32+line][2 chunks]
__device__ __align__(256) h16   g_hc[(size_t)64 * 16384];
__device__ __align__(256) float g_crow[2 * 32 * BB * HH];
__device__ __align__(256) float g_ccol[2 * 32 * BB * HH];
__device__ float    g_biasp[1024];
__device__ unsigned g_done[1024];

// ---------------- PTX helpers ----------------
__device__ __forceinline__ uint32_t smem_u32(const void* p) {
    uint32_t a;
    asm("{ .reg .u64 t; cvta.to.shared.u64 t, %1; cvt.u32.u64 %0, t; }" : "=r"(a) : "l"(p));
    return a;
}
#define MBAR_INIT(mbar, cnt) \
    asm volatile("mbarrier.init.shared.b64 [%0], %1;" :: "r"(mbar), "r"(cnt) : "memory")
#define MBAR_EXPECT(mbar, bytes) \
    asm volatile("mbarrier.arrive.expect_tx.shared.b64 _, [%0], %1;" :: "r"(mbar), "r"(bytes) : "memory")
__device__ __forceinline__ void tma_bulk(uint32_t dst, const void* src, uint32_t bytes, uint32_t mbar) {
    asm volatile("cp.async.bulk.shared::cta.global.mbarrier::complete_tx::bytes [%0], [%1], %2, [%3];"
                 :: "r"(dst), "l"(src), "r"(bytes), "r"(mbar) : "memory");
}
__device__ __forceinline__ void mbar_wait(uint32_t mbar, uint32_t parity) {
    uint32_t done;
    asm volatile(
        "{ .reg .pred p; mbarrier.try_wait.parity.acquire.cta.shared::cta.b64 p, [%1], %2;\n"
        "  selp.b32 %0, 1, 0, p; }"
        : "=r"(done) : "r"(mbar), "r"(parity) : "memory");
    if (!done) {
        asm volatile(
            "{ .reg .pred P1;\n"
            "WL_%=: mbarrier.try_wait.parity.acquire.cta.shared::cta.b64 P1, [%0], %1, 0x989680;\n"
            "@P1 bra.uni WD_%=;\n"
            "bra.uni WL_%=;\n"
            "WD_%=: }"
            :: "r"(mbar), "r"(parity) : "memory");
    }
}
#define LDSM4(r, addr) \
    asm volatile("ldmatrix.sync.aligned.m8n8.x4.shared.b16 {%0,%1,%2,%3}, [%4];" \
                 : "=r"((r)[0]), "=r"((r)[1]), "=r"((r)[2]), "=r"((r)[3]) : "r"(addr))
#define MMA(d, a, b0, b1) \
    asm volatile("mma.sync.aligned.m16n8k16.row.col.f32.f16.f16.f32 " \
                 "{%0,%1,%2,%3},{%4,%5,%6,%7},{%8,%9},{%0,%1,%2,%3};" \
                 : "+f"((d)[0]), "+f"((d)[1]), "+f"((d)[2]), "+f"((d)[3]) \
                 : "r"((a)[0]), "r"((a)[1]), "r"((a)[2]), "r"((a)[3]), "r"(b0), "r"(b1))

__device__ __forceinline__ float sigm_f(float x) { return __fdividef(1.0f, 1.0f + __expf(-x)); }
__device__ __forceinline__ float tanh_f(float x) { return fmaf(2.0f, sigm_f(2.0f * x), -1.0f); }

__device__ __forceinline__ void spinwait16(const unsigned* p) {
    unsigned v;
    do {
        asm volatile("ld.acquire.gpu.global.u32 %0, [%1];" : "=r"(v) : "l"(p) : "memory");
    } while (v < 16);
}

// permuted col p -> original gate row (verified mapping)
__device__ __forceinline__ int grow_of(int p) {
    int G = p >> 5, r5 = p & 31;
    return (r5 >> 3) * 256 + G * 8 + (r5 & 7);
}
// swizzled elem offset in a [rows x 64] chunk (128B rows)
__device__ __forceinline__ int swz64(int r, int c) {
    return r * 64 + ((((c >> 3) ^ (r & 7))) << 3) + (c & 7);
}

// ---------------- prep kernels ----------------
__global__ void k_prep_w(const float* __restrict__ wih, const float* __restrict__ whh,
                         const float* __restrict__ bih, const float* __restrict__ bhh) {
    int t = blockIdx.x * blockDim.x + threadIdx.x;   // 16*6*64*8 = 49152
    if (t >= 49152) return;
    int u = t & 7, r = (t >> 3) & 63, t3 = t >> 9;
    int chunk = t3 % 6, U = t3 / 6;
    int p = U * 64 + r, gr = grow_of(p);
    const float* src = (chunk < 2) ? (wih + (size_t)gr * 128 + chunk * 64 + u * 8)
                                   : (whh + (size_t)gr * 256 + (chunk - 2) * 64 + u * 8);
    unsigned short hv[8];
#pragma unroll
    for (int q = 0; q < 8; ++q) {
        h16 h = __float2half_rn(src[q]);
        hv[q] = *reinterpret_cast<unsigned short*>(&h);
    }
    h16* dst = g_w + (size_t)(U * 6 + chunk) * 4096 + r * 64 + ((u ^ (r & 7)) << 3);
    *reinterpret_cast<uint4*>(dst) = *reinterpret_cast<uint4*>(hv);
    if (chunk == 0 && u == 0) g_biasp[p] = bih[gr] + bhh[gr];
}

__global__ void k_prep_x(const float* __restrict__ x) {
    int t = blockIdx.x * blockDim.x + threadIdx.x;   // 1024*2*128*8 = 2M
    if (t >= 1024 * 2048) return;
    int u = t & 7, m = (t >> 3) & 127, chunk = (t >> 10) & 1, cell = t >> 11;
    const float* src = x + (size_t)cell * 16384 + m * 128 + chunk * 64 + u * 8;
    unsigned short hv[8];
#pragma unroll
    for (int q = 0; q < 8; ++q) {
        h16 h = __float2half_rn(src[q]);
        hv[q] = *reinterpret_cast<unsigned short*>(&h);
    }
    h16* dst = g_x + (size_t)cell * 16384 + chunk * 8192 + m * 64 + ((u ^ (m & 7)) << 3);
    *reinterpret_cast<uint4*>(dst) = *reinterpret_cast<uint4*>(hv);
}

__global__ void k_zero() {
    int t = blockIdx.x * blockDim.x + threadIdx.x;
    uint4 z = make_uint4(0, 0, 0, 0);
    if (t < 131072) {
        reinterpret_cast<uint4*>(g_hr)[t] = z;
        reinterpret_cast<uint4*>(g_hc)[t] = z;
    }
    if (t < 262144) {
        reinterpret_cast<uint4*>(g_crow)[t] = z;
        reinterpret_cast<uint4*>(g_ccol)[t] = z;
    }
    if (t < 1024) g_done[t] = 0;
}

// ---------------- persistent cell kernel ----------------
// Superstage: [A0 16K][A1 16K][B0 8K][B1 8K] = 48KB, 2 stages; mbars after.
#define STAGEB 49152
#define MBAR_OFF 98304
#define SMEM_TOTAL (98304 + 64)

__global__ __launch_bounds__(256, 2) void k_persist(int P) {
    extern __shared__ char smem[];
    uint32_t sb = smem_u32(smem);
    const uint32_t MB = sb + MBAR_OFF;
    int tid = threadIdx.x, lane = tid & 31, w = tid >> 5;
    int mw = w & 3, nw = w >> 2;
    int ar = lane & 15, au = lane >> 4;
    int brl = (lane & 7) + ((lane >> 4) << 3);
    int bu = (lane >> 3) & 1;

    if (tid == 0) { MBAR_INIT(MB, 1); MBAR_INIT(MB + 8, 1); }
    __syncthreads();

    int ph0 = 0, ph1 = 0;
    float acc[2][4][4];

    // issue one superstage: 2 A-chunks (contiguous 32KB) + 2 B-chunks (16KB)
    auto issueS = [&](const h16* a2, const h16* w2, int s) {
        uint32_t st = sb + s * STAGEB;
        uint32_t mb = MB + s * 8;
        MBAR_EXPECT(mb, 49152);
        tma_bulk(st, a2, 32768, mb);
        tma_bulk(st + 32768, w2, 16384, mb);
    };
    auto compute = [&](int s) {
        uint32_t st = sb + s * STAGEB;
#pragma unroll
        for (int sub = 0; sub < 2; ++sub) {
            uint32_t ab = st + sub * 16384;
            uint32_t bb = st + 32768 + sub * 8192;
#pragma unroll
            for (int ks = 0; ks < 4; ++ks) {
                uint32_t afr[2][4];
#pragma unroll
                for (int mt = 0; mt < 2; ++mt) {
                    int row = mw * 32 + mt * 16 + ar;
                    uint32_t u = ks * 2 + au;
                    LDSM4(afr[mt], ab + row * 128 + ((u ^ (row & 7)) << 4));
                }
                uint32_t bfr[2][4];
#pragma unroll
                for (int bt = 0; bt < 2; ++bt) {
                    int brow = nw * 32 + bt * 16 + brl;
                    uint32_t u2 = ks * 2 + bu;
                    LDSM4(bfr[bt], bb + brow * 128 + ((u2 ^ (brow & 7)) << 4));
                }
#pragma unroll
                for (int mt = 0; mt < 2; ++mt)
#pragma unroll
                    for (int f = 0; f < 4; ++f)
                        MMA(acc[mt][f], afr[mt], bfr[f >> 1][(f & 1) * 2], bfr[f >> 1][(f & 1) * 2 + 1]);
            }
        }
    };

    int b = blockIdx.x;
    for (int d = 0; d < 63; ++d) {
        int i0 = (d < 32) ? 0 : d - 31;
        int nd = (d < 32) ? d + 1 : 63 - d;
        int par = d & 1, qar = par ^ 1;
        for (int t = b; t < nd * 16; t += P) {
            int ci = i0 + (t >> 4);
            int j = d - ci;
            int U = t & 15;
            int cell = ci * 32 + j;
            const h16* wb = g_w + (size_t)U * 6 * 4096;

            // --- pre-dependency: x superstage (no dep on neighbors) ---
            if (tid == 0) issueS(g_x + (size_t)cell * 16384, wb, 0);
#pragma unroll
            for (int a = 0; a < 2; ++a)
#pragma unroll
                for (int f = 0; f < 4; ++f)
#pragma unroll
                    for (int e = 0; e < 4; ++e) acc[a][f][e] = 0.f;

            mbar_wait(MB, ph0); ph0 ^= 1;
            compute(0);
            __syncthreads();

            // --- dependency gate; both h superstages issue together ---
            if (tid == 0) {
                if (j > 0)  spinwait16(g_done + cell - 1);
                if (ci > 0) spinwait16(g_done + cell - 32);
                issueS(g_hr + (size_t)(par * 32 + ci) * 16384, wb + 8192, 1);
                issueS(g_hc + (size_t)(par * 32 + j) * 16384, wb + 16384, 0);
            }
            mbar_wait(MB + 8, ph1); ph1 ^= 1;
            compute(1);
            __syncthreads();
            mbar_wait(MB, ph0); ph0 ^= 1;
            compute(0);

            // ---- epilogue (verified mapping; h single fp16 now) ----
            bool isrow = (U < 8);
            int ub = (U & 7) * 16;
            int line = isrow ? ci : j;
            const float* csrc = (isrow ? g_crow : g_ccol) + (par * 32 + line) * (BB * HH);
            float* cdst       = (isrow ? g_crow : g_ccol) + (qar * 32 + line) * (BB * HH);
            h16* hdst         = (isrow ? g_hr : g_hc);
            size_t hb         = (size_t)(qar * 32 + line) * 16384;

#pragma unroll
            for (int mt = 0; mt < 2; ++mt) {
                int m0 = mw * 32 + mt * 16 + (lane >> 2);
#pragma unroll
                for (int dr = 0; dr < 2; ++dr) {
                    int m = m0 + dr * 8;
#pragma unroll
                    for (int du = 0; du < 2; ++du) {
                        int e = dr * 2 + du;
                        int wslot = (lane & 3) * 2 + du;
                        int pb = nw * 32 + wslot;
                        float I = acc[mt][0][e] + g_biasp[U * 64 + pb];
                        float F = acc[mt][1][e] + g_biasp[U * 64 + pb + 8];
                        float G = acc[mt][2][e] + g_biasp[U * 64 + pb + 16];
                        float O = acc[mt][3][e] + g_biasp[U * 64 + pb + 24];
                        int ug = ub + nw * 8 + wslot;
                        int cidx = m * HH + ug;
                        float cold = __ldcg(csrc + cidx);
                        float cn = sigm_f(F) * cold + sigm_f(I) * tanh_f(G);
                        float hn = sigm_f(O) * tanh_f(cn);
                        cdst[cidx] = cn;
                        size_t he = hb + (ug >> 6) * 8192 + swz64(m, ug & 63);
                        hdst[he] = __float2half_rn(hn);
                    }
                }
            }
            __syncthreads();   // writes done CTA-wide before release
            if (tid == 0)
                asm volatile("red.release.gpu.global.add.u32 [%0], %1;"
                             :: "l"(g_done + cell), "r"(1u) : "memory");
        }
    }
}

// ---------------- output pack ----------------
__global__ void k_out(float* __restrict__ out, int out_size) {
    int t = blockIdx.x * blockDim.x + threadIdx.x;
    if (t >= out_size) return;
    int sel = t >> 15;        // 0=h, 1=c
    int r = t & 32767;
    int m = r >> 8;
    int u = r & 255;
    float v;
    if (u < HH) {
        if (sel) v = g_crow[(32 + 31) * (BB * HH) + m * HH + u];
        else {
            size_t he = (size_t)63 * 16384 + (u >> 6) * 8192 + swz64(m, u & 63);
            v = __half2float(g_hr[he]);
        }
    } else {
        int uu = u - HH;
        if (sel) v = g_ccol[(32 + 31) * (BB * HH) + m * HH + uu];
        else {
            size_t he = (size_t)63 * 16384 + (uu >> 6) * 8192 + swz64(m, uu & 63);
            v = __half2float(g_hc[he]);
        }
    }
    out[t] = v;
}

// ---------------------------------------------------------------------------
extern "C" void kernel_launch(void* const* d_in, const int* in_sizes, int n_in,
                              void* d_out, int out_size) {
    const float* x   = (const float*)d_in[0];
    const float* wih = (const float*)d_in[1];
    const float* whh = (const float*)d_in[2];
    const float* bih = (const float*)d_in[3];
    const float* bhh = (const float*)d_in[4];

    cudaFuncSetAttribute(k_persist, cudaFuncAttributeMaxDynamicSharedMemorySize, SMEM_TOTAL);

    int dev = 0;
    cudaGetDevice(&dev);
    int nsm = 0;
    cudaDeviceGetAttribute(&nsm, cudaDevAttrMultiProcessorCount, dev);
    int occ = 0;
    cudaOccupancyMaxActiveBlocksPerMultiprocessor(&occ, k_persist, 256, SMEM_TOTAL);
    if (occ < 1) occ = 1;
    int P = nsm * occ;
    if (P > 512) P = 512;

    k_zero<<<1024, 256>>>();
    k_prep_w<<<192, 256>>>(wih, whh, bih, bhh);
    k_prep_x<<<8192, 256>>>(x);
    k_persist<<<P, 256, SMEM_TOTAL>>>(P);
    k_out<<<(out_size + 255) / 256, 256>>>((float*)d_out, out_size);
}